// round 7
// baseline (speedup 1.0000x reference)
#include <cuda_runtime.h>
#include <cstdint>

#define NN   25000
#define NE   100000
#define HD   32
#define NCL  8000
#define NA   50000
#define NEC  24000
#define EDIM 8

// ---------------- scratch (device globals; zero-initialized at load) -----------
__device__ float g_x[NN * HD];
__device__ float g_c[NCL * HD];
__device__ float g_h[(2 * NE + 2 * NEC) * HD];   // all 4 edge-MLP outputs
__device__ float g_P[(size_t)NN * HD * HD];      // 102.4 MB
__device__ float g_Q[NN * HD];
__device__ float g_aggn[NN * HD];                // kept zero between calls
__device__ float g_aggc[NCL * HD];               // kept zero between calls
__device__ float g_m[NN * HD];
__device__ int   g_deg[2 * NN + 2 * NCL];        // [dst | cdst | cid | nid]
__device__ int   g_cur[NN + NCL];                // CSR fill cursors [cur_c | cur_n]
__device__ int   g_off_c[NCL + 1];               // CSR offsets: assignments by cid
__device__ int   g_off_n[NN + 1];                // CSR offsets: assignments by nid
__device__ int   g_csr_c[NA];                    // by-cid: source node ids
__device__ int   g_csr_n[NA];                    // by-nid: source clique ids

// ---------------- setup ----------------------------------------------------------
__global__ void k_zero_setup(int* __restrict__ deg, int* __restrict__ cur) {
    int i = blockIdx.x * blockDim.x + threadIdx.x;
    if (i < 2 * NN + 2 * NCL) deg[i] = 0;
    if (i < NN + NCL) cur[i] = 0;
}

__global__ void k_count_all(const int* __restrict__ dst, const int* __restrict__ cdst,
                            const int* __restrict__ nid, const int* __restrict__ cid,
                            int* __restrict__ deg) {
    int i = blockIdx.x * blockDim.x + threadIdx.x;
    if (i < NE) {
        atomicAdd(&deg[dst[i]], 1);
    } else if (i < NE + NEC) {
        atomicAdd(&deg[NN + cdst[i - NE]], 1);
    } else if (i < NE + NEC + NA) {
        int j = i - NE - NEC;
        atomicAdd(&deg[NN + NCL + cid[j]], 1);
        atomicAdd(&deg[NN + 2 * NCL + nid[j]], 1);
    }
}

// two independent chunked inclusive scans -> exclusive offsets
__global__ void k_scan2(const int* __restrict__ degA, int nA_, int* __restrict__ offA,
                        const int* __restrict__ degB, int nB_, int* __restrict__ offB) {
    const int* deg; int n; int* off;
    if (blockIdx.x == 0) { deg = degA; n = nA_; off = offA; }
    else                 { deg = degB; n = nB_; off = offB; }
    __shared__ int s[1024];
    __shared__ int carry;
    int t = threadIdx.x;
    if (t == 0) { carry = 0; off[0] = 0; }
    __syncthreads();
    for (int base = 0; base < n; base += 1024) {
        int v = (base + t < n) ? deg[base + t] : 0;
        s[t] = v;
        __syncthreads();
        for (int d = 1; d < 1024; d <<= 1) {
            int add = (t >= d) ? s[t - d] : 0;
            __syncthreads();
            s[t] += add;
            __syncthreads();
        }
        if (base + t < n) off[base + t + 1] = carry + s[t];
        __syncthreads();
        if (t == 0) carry += s[1023];
        __syncthreads();
    }
}

__global__ void k_fill_csr(const int* __restrict__ nid, const int* __restrict__ cid,
                           const int* __restrict__ off_c, const int* __restrict__ off_n,
                           int* __restrict__ cur,
                           int* __restrict__ csr_c, int* __restrict__ csr_n) {
    int a = blockIdx.x * blockDim.x + threadIdx.x;
    if (a >= NA) return;
    int nd = nid[a], cl = cid[a];
    int p = atomicAdd(&cur[cl], 1);           // cur_c region [0, NCL)
    csr_c[off_c[cl] + p] = nd;
    int q = atomicAdd(&cur[NCL + nd], 1);     // cur_n region [NCL, NCL+NN)
    csr_n[off_n[nd] + q] = cl;
}

// ---------------- ALL edge MLPs (both graphs x both layers), warp per edge-row ----
__global__ void k_edge_mlp_all(const float* __restrict__ ef_n, const float* __restrict__ ef_c,
                               const float* __restrict__ nn1_w, const float* __restrict__ nn1_b,
                               const float* __restrict__ cnn1_w, const float* __restrict__ cnn1_b,
                               float* __restrict__ h) {
    int w = (blockIdx.x * blockDim.x + threadIdx.x) >> 5;
    int lane = threadIdx.x & 31;
    const float* ef; const float* w1; const float* b1; float* ho;
    if (w < 2 * NE) {
        int layer = w / NE, e = w - layer * NE;
        ef = ef_n + (size_t)e * EDIM;
        w1 = nn1_w + layer * EDIM * HD;
        b1 = nn1_b + layer * HD;
        ho = h + (size_t)(layer * NE + e) * HD;
    } else if (w < 2 * NE + 2 * NEC) {
        int w2 = w - 2 * NE;
        int layer = w2 / NEC, e = w2 - layer * NEC;
        ef = ef_c + (size_t)e * EDIM;
        w1 = cnn1_w + layer * EDIM * HD;
        b1 = cnn1_b + layer * HD;
        ho = h + (size_t)(2 * NE + layer * NEC + e) * HD;
    } else return;

    float ev = (lane < EDIM) ? ef[lane] : 0.f;
    float acc = b1[lane];
#pragma unroll
    for (int j = 0; j < EDIM; j++)
        acc += __shfl_sync(0xffffffffu, ev, j) * w1[j * HD + lane];
    ho[lane] = fmaxf(acc, 0.f);
}

// ---------------- P = X @ T (scalar FFMA, proven body) + Q slice -------------------
__global__ __launch_bounds__(256, 2)
void k_gemmPQ(const float* __restrict__ X, int nrows,
              const float* __restrict__ w2, const float* __restrict__ b2,
              float* __restrict__ P, float* __restrict__ Q) {
    int tid  = threadIdx.x;
    int row0 = blockIdx.x * 128;

    if (blockIdx.y == 8) {
        int wp = tid >> 5, lane = tid & 31;
        for (int it = 0; it < 16; it++) {
            int r = row0 + it * 8 + wp;
            if (r >= nrows) return;
            float xv = X[(size_t)r * HD + lane];
            float acc = 0.f;
#pragma unroll
            for (int i = 0; i < HD; i++)
                acc += __shfl_sync(0xffffffffu, xv, i) * b2[i * HD + lane];
            Q[(size_t)r * HD + lane] = acc;
        }
        return;
    }

    __shared__ float As[HD][128];
    __shared__ float Bs[HD][128];
    int col0 = blockIdx.y * 128;

    {
        int r = tid >> 3;
        int q = tid & 7;
        for (int rr = r; rr < 128; rr += 32) {
            int row = row0 + rr;
            float4 v = make_float4(0.f, 0.f, 0.f, 0.f);
            if (row < nrows) v = *(const float4*)(X + (size_t)row * HD + q * 4);
            As[q * 4 + 0][rr] = v.x;
            As[q * 4 + 1][rr] = v.y;
            As[q * 4 + 2][rr] = v.z;
            As[q * 4 + 3][rr] = v.w;
        }
    }
    {
        int r = tid >> 5;
        int q = tid & 31;
        int C = col0 + q * 4;
        int kcol = C >> 5, o = C & 31;
        for (int kk = r; kk < HD; kk += 8) {
            float4 v = *(const float4*)(w2 + kcol * (HD * HD) + kk * HD + o);
            *(float4*)&Bs[kk][q * 4] = v;
        }
    }
    __syncthreads();

    int tr = (tid >> 4) * 8;
    int tc = (tid & 15) * 8;
    float acc[8][8];
#pragma unroll
    for (int a = 0; a < 8; a++)
#pragma unroll
        for (int b = 0; b < 8; b++) acc[a][b] = 0.f;

#pragma unroll
    for (int k = 0; k < HD; k++) {
        float a[8], b[8];
        *(float4*)&a[0] = *(float4*)&As[k][tr];
        *(float4*)&a[4] = *(float4*)&As[k][tr + 4];
        *(float4*)&b[0] = *(float4*)&Bs[k][tc];
        *(float4*)&b[4] = *(float4*)&Bs[k][tc + 4];
#pragma unroll
        for (int i = 0; i < 8; i++)
#pragma unroll
            for (int j = 0; j < 8; j++)
                acc[i][j] += a[i] * b[j];
    }

#pragma unroll
    for (int i = 0; i < 8; i++) {
        int row = row0 + tr + i;
        if (row < nrows) {
            float* dstp = P + (size_t)row * (HD * HD) + col0 + tc;
            *(float4*)(dstp)     = make_float4(acc[i][0], acc[i][1], acc[i][2], acc[i][3]);
            *(float4*)(dstp + 4) = make_float4(acc[i][4], acc[i][5], acc[i][6], acc[i][7]);
        }
    }
}

// ---------------- per-edge message + scatter-add (proven) -------------------------
__global__ void k_edge_msg(int nE, const int* __restrict__ src, const int* __restrict__ dst,
                           const float* __restrict__ h, const float* __restrict__ P,
                           const float* __restrict__ Q, float* __restrict__ agg) {
    int e = (blockIdx.x * blockDim.x + threadIdx.x) >> 5;
    int lane = threadIdx.x & 31;
    if (e >= nE) return;
    int s = src[e];
    int d = dst[e];
    float hv = h[(size_t)e * HD + lane];
    const float4* Pr = (const float4*)(P + (size_t)s * (HD * HD));
    int kq = lane >> 3;
    int og = lane & 7;

    float a0 = 0.f, a1 = 0.f, a2 = 0.f, a3 = 0.f;
#pragma unroll
    for (int it = 0; it < 8; it++) {
        int k = it * 4 + kq;
        float hk = __shfl_sync(0xffffffffu, hv, k);
        float4 v = Pr[k * 8 + og];
        a0 += hk * v.x; a1 += hk * v.y; a2 += hk * v.z; a3 += hk * v.w;
    }
#pragma unroll
    for (int m = 8; m <= 16; m <<= 1) {
        a0 += __shfl_xor_sync(0xffffffffu, a0, m);
        a1 += __shfl_xor_sync(0xffffffffu, a1, m);
        a2 += __shfl_xor_sync(0xffffffffu, a2, m);
        a3 += __shfl_xor_sync(0xffffffffu, a3, m);
    }
    if (lane < 8) {
        float4 q = *(const float4*)(Q + (size_t)s * HD + lane * 4);
        float* ag = agg + (size_t)d * HD + lane * 4;
        atomicAdd(ag + 0, a0 + q.x);
        atomicAdd(ag + 1, a1 + q.y);
        atomicAdd(ag + 2, a2 + q.z);
        atomicAdd(ag + 3, a3 + q.w);
    }
}

// ---------------- finalize + project; re-zeros agg after consuming ----------------
__global__ void k_finalize_proj(const float* __restrict__ Xin, float* __restrict__ Xout,
                                float* __restrict__ agg, const int* __restrict__ deg,
                                const float* __restrict__ rw, const float* __restrict__ rb,
                                const float* __restrict__ pw, const float* __restrict__ pb,
                                float* __restrict__ m, int nrows,
                                float* __restrict__ copy_out) {
    __shared__ float Rs[HD][HD], Pw[HD][HD];
    for (int i = threadIdx.x; i < HD * HD; i += blockDim.x) {
        Rs[i >> 5][i & 31] = rw[i];
        Pw[i >> 5][i & 31] = pw[i];
    }
    __syncthreads();

    int r = (blockIdx.x * blockDim.x + threadIdx.x) >> 5;
    int lane = threadIdx.x & 31;
    if (r >= nrows) return;
    float xv = Xin[(size_t)r * HD + lane];
    float av = agg[(size_t)r * HD + lane];
    agg[(size_t)r * HD + lane] = 0.f;            // restore zero invariant
    float acc = rb[lane] + av / fmaxf((float)deg[r], 1.f);
#pragma unroll
    for (int i = 0; i < HD; i++)
        acc += __shfl_sync(0xffffffffu, xv, i) * Rs[i][lane];
    float xn = fmaxf(acc, 0.f);
    Xout[(size_t)r * HD + lane] = xn;
    if (copy_out) copy_out[(size_t)r * HD + lane] = xn;
    float macc = pb[lane];
#pragma unroll
    for (int i = 0; i < HD; i++)
        macc += __shfl_sync(0xffffffffu, xn, i) * Pw[i][lane];
    m[(size_t)r * HD + lane] = macc;
}

// ---------------- CSR gather segment-mean + residual add --------------------------
// out[r] = in[r] + mean_{j in csr[off[r]:off[r+1]]} m[csr[j]]
__global__ void k_seg_mean_add(const float* __restrict__ in, float* __restrict__ outp,
                               const float* __restrict__ m,
                               const int* __restrict__ off, const int* __restrict__ csr,
                               int nrows) {
    int r = (blockIdx.x * blockDim.x + threadIdx.x) >> 5;
    int lane = threadIdx.x & 31;
    if (r >= nrows) return;
    int b = off[r], e2 = off[r + 1];
    float acc = 0.f;
    for (int j = b; j < e2; j++)
        acc += m[(size_t)csr[j] * HD + lane];
    outp[(size_t)r * HD + lane] =
        in[(size_t)r * HD + lane] + acc / fmaxf((float)(e2 - b), 1.f);
}

// ===================================================================================
static inline int cdiv(int a, int b) { return (a + b - 1) / b; }

extern "C" void kernel_launch(void* const* d_in, const int* in_sizes, int n_in,
                              void* d_out, int out_size) {
    const float* node_features   = (const float*)d_in[0];
    const int*   edge_index      = (const int*)d_in[1];
    const float* edge_features   = (const float*)d_in[2];
    const float* clique_features = (const float*)d_in[3];
    const int*   n2c_index       = (const int*)d_in[4];
    const int*   cedge_index     = (const int*)d_in[5];
    const float* cedge_features  = (const float*)d_in[6];
    const float* nn1_w  = (const float*)d_in[7];
    const float* nn1_b  = (const float*)d_in[8];
    const float* nn2_w  = (const float*)d_in[9];
    const float* nn2_b  = (const float*)d_in[10];
    const float* root_w = (const float*)d_in[11];
    const float* root_b = (const float*)d_in[12];
    const float* n2c_w  = (const float*)d_in[13];
    const float* n2c_b  = (const float*)d_in[14];
    const float* cnn1_w = (const float*)d_in[15];
    const float* cnn1_b = (const float*)d_in[16];
    const float* cnn2_w = (const float*)d_in[17];
    const float* cnn2_b = (const float*)d_in[18];
    const float* croot_w = (const float*)d_in[19];
    const float* croot_b = (const float*)d_in[20];
    const float* c2n_w  = (const float*)d_in[21];
    const float* c2n_b  = (const float*)d_in[22];
    float* out = (float*)d_out;

    const int* src  = edge_index;
    const int* dst  = edge_index + NE;
    const int* nid  = n2c_index;
    const int* cid  = n2c_index + NA;
    const int* csrc = cedge_index;
    const int* cdst = cedge_index + NEC;

    float *x, *c, *h, *P, *Q, *aggn, *aggc, *m;
    int *deg, *cur, *off_c, *off_n, *csr_c, *csr_n;
    cudaGetSymbolAddress((void**)&x, g_x);
    cudaGetSymbolAddress((void**)&c, g_c);
    cudaGetSymbolAddress((void**)&h, g_h);
    cudaGetSymbolAddress((void**)&P, g_P);
    cudaGetSymbolAddress((void**)&Q, g_Q);
    cudaGetSymbolAddress((void**)&aggn, g_aggn);
    cudaGetSymbolAddress((void**)&aggc, g_aggc);
    cudaGetSymbolAddress((void**)&m, g_m);
    cudaGetSymbolAddress((void**)&deg, g_deg);
    cudaGetSymbolAddress((void**)&cur, g_cur);
    cudaGetSymbolAddress((void**)&off_c, g_off_c);
    cudaGetSymbolAddress((void**)&off_n, g_off_n);
    cudaGetSymbolAddress((void**)&csr_c, g_csr_c);
    cudaGetSymbolAddress((void**)&csr_n, g_csr_n);
    const int* deg_dst  = deg;
    const int* deg_cdst = deg + NN;
    const int* deg_cid  = deg + NN + NCL;
    const int* deg_nid  = deg + NN + 2 * NCL;

    const int TB = 256;
    dim3 gemmGridN(cdiv(NN, 128), 9);   // y==8 is the Q slice
    dim3 gemmGridC(cdiv(NCL, 128), 9);

    // ---- launch order (edge_msg is #4 -> profiled by ncu) ----
    // 1: all edge MLPs (needs only edge features)
    k_edge_mlp_all<<<cdiv((2 * NE + 2 * NEC) * 32, TB), TB>>>(
        edge_features, cedge_features, nn1_w, nn1_b, cnn1_w, cnn1_b, h);
    // 2: node gemm l0 (reads input features directly)
    k_gemmPQ<<<gemmGridN, 256>>>(node_features, NN, nn2_w, nn2_b, P, Q);
    // 3: zero deg + cursors
    k_zero_setup<<<cdiv(2 * NN + 2 * NCL, TB), TB>>>(deg, cur);
    // 4: node edge messages l0  <-- PROFILED
    k_edge_msg<<<cdiv(NE * 32, TB), TB>>>(NE, src, dst, h, P, Q, aggn);
    // 5-7: degree counts, CSR offsets, CSR fill
    k_count_all<<<cdiv(NE + NEC + NA, TB), TB>>>(dst, cdst, nid, cid, deg);
    k_scan2<<<2, 1024>>>(deg_cid, NCL, off_c, deg_nid, NN, off_n);
    k_fill_csr<<<cdiv(NA, TB), TB>>>(nid, cid, off_c, off_n, cur, csr_c, csr_n);
    // 8: finalize x l0 + project m
    k_finalize_proj<<<cdiv(NN * 32, TB), TB>>>(node_features, x, aggn, deg_dst,
                                               root_w, root_b, n2c_w, n2c_b,
                                               m, NN, nullptr);
    // 9: c = clique_features + segment_mean(m by cid)
    k_seg_mean_add<<<cdiv(NCL * 32, TB), TB>>>(clique_features, c, m, off_c, csr_c, NCL);

    // ---- l0 clique conv ----
    k_gemmPQ<<<gemmGridC, 256>>>(c, NCL, cnn2_w, cnn2_b, P, Q);
    k_edge_msg<<<cdiv(NEC * 32, TB), TB>>>(NEC, csrc, cdst, h + (size_t)2 * NE * HD, P, Q, aggc);
    k_finalize_proj<<<cdiv(NCL * 32, TB), TB>>>(c, c, aggc, deg_cdst,
                                                croot_w, croot_b, c2n_w, c2n_b,
                                                m, NCL, nullptr);
    k_seg_mean_add<<<cdiv(NN * 32, TB), TB>>>(x, x, m, off_n, csr_n, NN);

    // ---- l1 node conv ----
    k_gemmPQ<<<gemmGridN, 256>>>(x, NN, nn2_w + HD * HD * HD, nn2_b + HD * HD, P, Q);
    k_edge_msg<<<cdiv(NE * 32, TB), TB>>>(NE, src, dst, h + (size_t)NE * HD, P, Q, aggn);
    k_finalize_proj<<<cdiv(NN * 32, TB), TB>>>(x, x, aggn, deg_dst,
                                               root_w + HD * HD, root_b + HD,
                                               n2c_w + HD * HD, n2c_b + HD,
                                               m, NN, nullptr);
    k_seg_mean_add<<<cdiv(NCL * 32, TB), TB>>>(c, c, m, off_c, csr_c, NCL);

    // ---- l1 clique conv ----
    k_gemmPQ<<<gemmGridC, 256>>>(c, NCL, cnn2_w + HD * HD * HD, cnn2_b + HD * HD, P, Q);
    k_edge_msg<<<cdiv(NEC * 32, TB), TB>>>(NEC, csrc, cdst,
                                           h + (size_t)(2 * NE + NEC) * HD, P, Q, aggc);
    // final c written into out as well
    k_finalize_proj<<<cdiv(NCL * 32, TB), TB>>>(c, c, aggc, deg_cdst,
                                                croot_w + HD * HD, croot_b + HD,
                                                c2n_w + HD * HD, c2n_b + HD,
                                                m, NCL, out + (size_t)NN * HD);
    // final x written into out
    k_seg_mean_add<<<cdiv(NN * 32, TB), TB>>>(x, out, m, off_n, csr_n, NN);
}

// round 8
// speedup vs baseline: 1.1674x; 1.1674x over previous
#include <cuda_runtime.h>
#include <cuda_fp16.h>
#include <cstdint>

#define NN   25000
#define NE   100000
#define HD   32
#define NCL  8000
#define NA   50000
#define NEC  24000
#define EDIM 8

// ---------------- scratch (device globals; zero-initialized at load) -----------
__device__ float  g_x[NN * HD];
__device__ float  g_c[NCL * HD];
__device__ float  g_h[(2 * NE + 2 * NEC) * HD];   // all 4 edge-MLP outputs
__device__ __half g_P[(size_t)NN * HD * HD];      // 51.2 MB (fp16 P)
__device__ float  g_Q[NN * HD];
__device__ float  g_aggn[NN * HD];                // kept zero between calls
__device__ float  g_aggc[NCL * HD];               // kept zero between calls
__device__ float  g_m[NN * HD];
__device__ int    g_deg[2 * NN + 2 * NCL];        // [dst | cdst | cid | nid]
__device__ int    g_cur[NN + NCL];                // CSR fill cursors [cur_c | cur_n]
__device__ int    g_off_c[NCL + 1];
__device__ int    g_off_n[NN + 1];
__device__ int    g_csr_c[NA];
__device__ int    g_csr_n[NA];

// ---------------- setup ----------------------------------------------------------
__global__ void k_zero_setup(int* __restrict__ deg, int* __restrict__ cur) {
    int i = blockIdx.x * blockDim.x + threadIdx.x;
    if (i < 2 * NN + 2 * NCL) deg[i] = 0;
    if (i < NN + NCL) cur[i] = 0;
}

__global__ void k_count_all(const int* __restrict__ dst, const int* __restrict__ cdst,
                            const int* __restrict__ nid, const int* __restrict__ cid,
                            int* __restrict__ deg) {
    int i = blockIdx.x * blockDim.x + threadIdx.x;
    if (i < NE) {
        atomicAdd(&deg[dst[i]], 1);
    } else if (i < NE + NEC) {
        atomicAdd(&deg[NN + cdst[i - NE]], 1);
    } else if (i < NE + NEC + NA) {
        int j = i - NE - NEC;
        atomicAdd(&deg[NN + NCL + cid[j]], 1);
        atomicAdd(&deg[NN + 2 * NCL + nid[j]], 1);
    }
}

// two independent chunked inclusive scans -> exclusive offsets
__global__ void k_scan2(const int* __restrict__ degA, int nA_, int* __restrict__ offA,
                        const int* __restrict__ degB, int nB_, int* __restrict__ offB) {
    const int* deg; int n; int* off;
    if (blockIdx.x == 0) { deg = degA; n = nA_; off = offA; }
    else                 { deg = degB; n = nB_; off = offB; }
    __shared__ int s[1024];
    __shared__ int carry;
    int t = threadIdx.x;
    if (t == 0) { carry = 0; off[0] = 0; }
    __syncthreads();
    for (int base = 0; base < n; base += 1024) {
        int v = (base + t < n) ? deg[base + t] : 0;
        s[t] = v;
        __syncthreads();
        for (int d = 1; d < 1024; d <<= 1) {
            int add = (t >= d) ? s[t - d] : 0;
            __syncthreads();
            s[t] += add;
            __syncthreads();
        }
        if (base + t < n) off[base + t + 1] = carry + s[t];
        __syncthreads();
        if (t == 0) carry += s[1023];
        __syncthreads();
    }
}

__global__ void k_fill_csr(const int* __restrict__ nid, const int* __restrict__ cid,
                           const int* __restrict__ off_c, const int* __restrict__ off_n,
                           int* __restrict__ cur,
                           int* __restrict__ csr_c, int* __restrict__ csr_n) {
    int a = blockIdx.x * blockDim.x + threadIdx.x;
    if (a >= NA) return;
    int nd = nid[a], cl = cid[a];
    int p = atomicAdd(&cur[cl], 1);
    csr_c[off_c[cl] + p] = nd;
    int q = atomicAdd(&cur[NCL + nd], 1);
    csr_n[off_n[nd] + q] = cl;
}

// ---------------- ALL edge MLPs (both graphs x both layers), warp per edge-row ----
__global__ void k_edge_mlp_all(const float* __restrict__ ef_n, const float* __restrict__ ef_c,
                               const float* __restrict__ nn1_w, const float* __restrict__ nn1_b,
                               const float* __restrict__ cnn1_w, const float* __restrict__ cnn1_b,
                               float* __restrict__ h) {
    int w = (blockIdx.x * blockDim.x + threadIdx.x) >> 5;
    int lane = threadIdx.x & 31;
    const float* ef; const float* w1; const float* b1; float* ho;
    if (w < 2 * NE) {
        int layer = w / NE, e = w - layer * NE;
        ef = ef_n + (size_t)e * EDIM;
        w1 = nn1_w + layer * EDIM * HD;
        b1 = nn1_b + layer * HD;
        ho = h + (size_t)(layer * NE + e) * HD;
    } else if (w < 2 * NE + 2 * NEC) {
        int w2 = w - 2 * NE;
        int layer = w2 / NEC, e = w2 - layer * NEC;
        ef = ef_c + (size_t)e * EDIM;
        w1 = cnn1_w + layer * EDIM * HD;
        b1 = cnn1_b + layer * HD;
        ho = h + (size_t)(2 * NE + layer * NEC + e) * HD;
    } else return;

    float ev = (lane < EDIM) ? ef[lane] : 0.f;
    float acc = b1[lane];
#pragma unroll
    for (int j = 0; j < EDIM; j++)
        acc += __shfl_sync(0xffffffffu, ev, j) * w1[j * HD + lane];
    ho[lane] = fmaxf(acc, 0.f);
}

// ---------------- P = X @ T (fp32 compute, fp16 store) + Q slice -------------------
__global__ __launch_bounds__(256, 2)
void k_gemmPQ(const float* __restrict__ X, int nrows,
              const float* __restrict__ w2, const float* __restrict__ b2,
              __half* __restrict__ P, float* __restrict__ Q) {
    int tid  = threadIdx.x;
    int row0 = blockIdx.x * 128;

    if (blockIdx.y == 8) {
        int wp = tid >> 5, lane = tid & 31;
        for (int it = 0; it < 16; it++) {
            int r = row0 + it * 8 + wp;
            if (r >= nrows) return;
            float xv = X[(size_t)r * HD + lane];
            float acc = 0.f;
#pragma unroll
            for (int i = 0; i < HD; i++)
                acc += __shfl_sync(0xffffffffu, xv, i) * b2[i * HD + lane];
            Q[(size_t)r * HD + lane] = acc;
        }
        return;
    }

    __shared__ float As[HD][128];
    __shared__ float Bs[HD][128];
    int col0 = blockIdx.y * 128;

    {
        int r = tid >> 3;
        int q = tid & 7;
        for (int rr = r; rr < 128; rr += 32) {
            int row = row0 + rr;
            float4 v = make_float4(0.f, 0.f, 0.f, 0.f);
            if (row < nrows) v = *(const float4*)(X + (size_t)row * HD + q * 4);
            As[q * 4 + 0][rr] = v.x;
            As[q * 4 + 1][rr] = v.y;
            As[q * 4 + 2][rr] = v.z;
            As[q * 4 + 3][rr] = v.w;
        }
    }
    {
        int r = tid >> 5;
        int q = tid & 31;
        int C = col0 + q * 4;
        int kcol = C >> 5, o = C & 31;
        for (int kk = r; kk < HD; kk += 8) {
            float4 v = *(const float4*)(w2 + kcol * (HD * HD) + kk * HD + o);
            *(float4*)&Bs[kk][q * 4] = v;
        }
    }
    __syncthreads();

    int tr = (tid >> 4) * 8;
    int tc = (tid & 15) * 8;
    float acc[8][8];
#pragma unroll
    for (int a = 0; a < 8; a++)
#pragma unroll
        for (int b = 0; b < 8; b++) acc[a][b] = 0.f;

#pragma unroll
    for (int k = 0; k < HD; k++) {
        float a[8], b[8];
        *(float4*)&a[0] = *(float4*)&As[k][tr];
        *(float4*)&a[4] = *(float4*)&As[k][tr + 4];
        *(float4*)&b[0] = *(float4*)&Bs[k][tc];
        *(float4*)&b[4] = *(float4*)&Bs[k][tc + 4];
#pragma unroll
        for (int i = 0; i < 8; i++)
#pragma unroll
            for (int j = 0; j < 8; j++)
                acc[i][j] += a[i] * b[j];
    }

#pragma unroll
    for (int i = 0; i < 8; i++) {
        int row = row0 + tr + i;
        if (row < nrows) {
            __half2 h0 = __floats2half2_rn(acc[i][0], acc[i][1]);
            __half2 h1 = __floats2half2_rn(acc[i][2], acc[i][3]);
            __half2 h2 = __floats2half2_rn(acc[i][4], acc[i][5]);
            __half2 h3 = __floats2half2_rn(acc[i][6], acc[i][7]);
            uint4 pk;
            pk.x = *(unsigned*)&h0; pk.y = *(unsigned*)&h1;
            pk.z = *(unsigned*)&h2; pk.w = *(unsigned*)&h3;
            *(uint4*)(P + (size_t)row * (HD * HD) + col0 + tc) = pk;
        }
    }
}

// ---------------- per-edge message + scatter-add (fp16 P gather) ------------------
__global__ void k_edge_msg(int nE, const int* __restrict__ src, const int* __restrict__ dst,
                           const float* __restrict__ h, const __half* __restrict__ P,
                           const float* __restrict__ Q, float* __restrict__ agg) {
    int e = (blockIdx.x * blockDim.x + threadIdx.x) >> 5;
    int lane = threadIdx.x & 31;
    if (e >= nE) return;
    int s = src[e];
    int d = dst[e];
    float hv = h[(size_t)e * HD + lane];
    const __half* Pr = P + (size_t)s * (HD * HD);
    int kq = lane >> 3;
    int og = lane & 7;

    float a0 = 0.f, a1 = 0.f, a2 = 0.f, a3 = 0.f;
#pragma unroll
    for (int it = 0; it < 8; it++) {
        int k = it * 4 + kq;
        float hk = __shfl_sync(0xffffffffu, hv, k);
        uint2 raw = *(const uint2*)(Pr + k * HD + og * 4);   // 4 halves, 8B aligned
        float2 f01 = __half22float2(*(__half2*)&raw.x);
        float2 f23 = __half22float2(*(__half2*)&raw.y);
        a0 += hk * f01.x; a1 += hk * f01.y; a2 += hk * f23.x; a3 += hk * f23.y;
    }
#pragma unroll
    for (int m = 8; m <= 16; m <<= 1) {
        a0 += __shfl_xor_sync(0xffffffffu, a0, m);
        a1 += __shfl_xor_sync(0xffffffffu, a1, m);
        a2 += __shfl_xor_sync(0xffffffffu, a2, m);
        a3 += __shfl_xor_sync(0xffffffffu, a3, m);
    }
    if (lane < 8) {
        float4 q = *(const float4*)(Q + (size_t)s * HD + lane * 4);
        float* ag = agg + (size_t)d * HD + lane * 4;
        atomicAdd(ag + 0, a0 + q.x);
        atomicAdd(ag + 1, a1 + q.y);
        atomicAdd(ag + 2, a2 + q.z);
        atomicAdd(ag + 3, a3 + q.w);
    }
}

// ---------------- finalize + project; re-zeros agg after consuming ----------------
__global__ void k_finalize_proj(const float* __restrict__ Xin, float* __restrict__ Xout,
                                float* __restrict__ agg, const int* __restrict__ deg,
                                const float* __restrict__ rw, const float* __restrict__ rb,
                                const float* __restrict__ pw, const float* __restrict__ pb,
                                float* __restrict__ m, int nrows,
                                float* __restrict__ copy_out) {
    __shared__ float Rs[HD][HD], Pw[HD][HD];
    for (int i = threadIdx.x; i < HD * HD; i += blockDim.x) {
        Rs[i >> 5][i & 31] = rw[i];
        Pw[i >> 5][i & 31] = pw[i];
    }
    __syncthreads();

    int r = (blockIdx.x * blockDim.x + threadIdx.x) >> 5;
    int lane = threadIdx.x & 31;
    if (r >= nrows) return;
    float xv = Xin[(size_t)r * HD + lane];
    float av = agg[(size_t)r * HD + lane];
    agg[(size_t)r * HD + lane] = 0.f;            // restore zero invariant
    float acc = rb[lane] + av / fmaxf((float)deg[r], 1.f);
#pragma unroll
    for (int i = 0; i < HD; i++)
        acc += __shfl_sync(0xffffffffu, xv, i) * Rs[i][lane];
    float xn = fmaxf(acc, 0.f);
    Xout[(size_t)r * HD + lane] = xn;
    if (copy_out) copy_out[(size_t)r * HD + lane] = xn;
    float macc = pb[lane];
#pragma unroll
    for (int i = 0; i < HD; i++)
        macc += __shfl_sync(0xffffffffu, xn, i) * Pw[i][lane];
    m[(size_t)r * HD + lane] = macc;
}

// ---------------- CSR gather segment-mean + residual add --------------------------
__global__ void k_seg_mean_add(const float* __restrict__ in, float* __restrict__ outp,
                               const float* __restrict__ m,
                               const int* __restrict__ off, const int* __restrict__ csr,
                               int nrows) {
    int r = (blockIdx.x * blockDim.x + threadIdx.x) >> 5;
    int lane = threadIdx.x & 31;
    if (r >= nrows) return;
    int b = off[r], e2 = off[r + 1];
    float acc = 0.f;
    for (int j = b; j < e2; j++)
        acc += m[(size_t)csr[j] * HD + lane];
    outp[(size_t)r * HD + lane] =
        in[(size_t)r * HD + lane] + acc / fmaxf((float)(e2 - b), 1.f);
}

// ===================================================================================
static inline int cdiv(int a, int b) { return (a + b - 1) / b; }

extern "C" void kernel_launch(void* const* d_in, const int* in_sizes, int n_in,
                              void* d_out, int out_size) {
    const float* node_features   = (const float*)d_in[0];
    const int*   edge_index      = (const int*)d_in[1];
    const float* edge_features   = (const float*)d_in[2];
    const float* clique_features = (const float*)d_in[3];
    const int*   n2c_index       = (const int*)d_in[4];
    const int*   cedge_index     = (const int*)d_in[5];
    const float* cedge_features  = (const float*)d_in[6];
    const float* nn1_w  = (const float*)d_in[7];
    const float* nn1_b  = (const float*)d_in[8];
    const float* nn2_w  = (const float*)d_in[9];
    const float* nn2_b  = (const float*)d_in[10];
    const float* root_w = (const float*)d_in[11];
    const float* root_b = (const float*)d_in[12];
    const float* n2c_w  = (const float*)d_in[13];
    const float* n2c_b  = (const float*)d_in[14];
    const float* cnn1_w = (const float*)d_in[15];
    const float* cnn1_b = (const float*)d_in[16];
    const float* cnn2_w = (const float*)d_in[17];
    const float* cnn2_b = (const float*)d_in[18];
    const float* croot_w = (const float*)d_in[19];
    const float* croot_b = (const float*)d_in[20];
    const float* c2n_w  = (const float*)d_in[21];
    const float* c2n_b  = (const float*)d_in[22];
    float* out = (float*)d_out;

    const int* src  = edge_index;
    const int* dst  = edge_index + NE;
    const int* nid  = n2c_index;
    const int* cid  = n2c_index + NA;
    const int* csrc = cedge_index;
    const int* cdst = cedge_index + NEC;

    float *x, *c, *h, *Q, *aggn, *aggc, *m;
    __half* P;
    int *deg, *cur, *off_c, *off_n, *csr_c, *csr_n;
    cudaGetSymbolAddress((void**)&x, g_x);
    cudaGetSymbolAddress((void**)&c, g_c);
    cudaGetSymbolAddress((void**)&h, g_h);
    cudaGetSymbolAddress((void**)&P, g_P);
    cudaGetSymbolAddress((void**)&Q, g_Q);
    cudaGetSymbolAddress((void**)&aggn, g_aggn);
    cudaGetSymbolAddress((void**)&aggc, g_aggc);
    cudaGetSymbolAddress((void**)&m, g_m);
    cudaGetSymbolAddress((void**)&deg, g_deg);
    cudaGetSymbolAddress((void**)&cur, g_cur);
    cudaGetSymbolAddress((void**)&off_c, g_off_c);
    cudaGetSymbolAddress((void**)&off_n, g_off_n);
    cudaGetSymbolAddress((void**)&csr_c, g_csr_c);
    cudaGetSymbolAddress((void**)&csr_n, g_csr_n);
    const int* deg_dst  = deg;
    const int* deg_cdst = deg + NN;
    const int* deg_cid  = deg + NN + NCL;
    const int* deg_nid  = deg + NN + 2 * NCL;

    const int TB = 256;
    dim3 gemmGridN(cdiv(NN, 128), 9);   // y==8 is the Q slice
    dim3 gemmGridC(cdiv(NCL, 128), 9);

    // ---- launch order (edge_msg is #4 -> profiled by ncu) ----
    k_edge_mlp_all<<<cdiv((2 * NE + 2 * NEC) * 32, TB), TB>>>(
        edge_features, cedge_features, nn1_w, nn1_b, cnn1_w, cnn1_b, h);
    k_gemmPQ<<<gemmGridN, 256>>>(node_features, NN, nn2_w, nn2_b, P, Q);
    k_zero_setup<<<cdiv(2 * NN + 2 * NCL, TB), TB>>>(deg, cur);
    // 4: node edge messages l0  <-- PROFILED
    k_edge_msg<<<cdiv(NE * 32, TB), TB>>>(NE, src, dst, h, P, Q, aggn);
    k_count_all<<<cdiv(NE + NEC + NA, TB), TB>>>(dst, cdst, nid, cid, deg);
    k_scan2<<<2, 1024>>>(deg_cid, NCL, off_c, deg_nid, NN, off_n);
    k_fill_csr<<<cdiv(NA, TB), TB>>>(nid, cid, off_c, off_n, cur, csr_c, csr_n);
    k_finalize_proj<<<cdiv(NN * 32, TB), TB>>>(node_features, x, aggn, deg_dst,
                                               root_w, root_b, n2c_w, n2c_b,
                                               m, NN, nullptr);
    k_seg_mean_add<<<cdiv(NCL * 32, TB), TB>>>(clique_features, c, m, off_c, csr_c, NCL);

    // ---- l0 clique conv ----
    k_gemmPQ<<<gemmGridC, 256>>>(c, NCL, cnn2_w, cnn2_b, P, Q);
    k_edge_msg<<<cdiv(NEC * 32, TB), TB>>>(NEC, csrc, cdst, h + (size_t)2 * NE * HD, P, Q, aggc);
    k_finalize_proj<<<cdiv(NCL * 32, TB), TB>>>(c, c, aggc, deg_cdst,
                                                croot_w, croot_b, c2n_w, c2n_b,
                                                m, NCL, nullptr);
    k_seg_mean_add<<<cdiv(NN * 32, TB), TB>>>(x, x, m, off_n, csr_n, NN);

    // ---- l1 node conv ----
    k_gemmPQ<<<gemmGridN, 256>>>(x, NN, nn2_w + HD * HD * HD, nn2_b + HD * HD, P, Q);
    k_edge_msg<<<cdiv(NE * 32, TB), TB>>>(NE, src, dst, h + (size_t)NE * HD, P, Q, aggn);
    k_finalize_proj<<<cdiv(NN * 32, TB), TB>>>(x, x, aggn, deg_dst,
                                               root_w + HD * HD, root_b + HD,
                                               n2c_w + HD * HD, n2c_b + HD,
                                               m, NN, nullptr);
    k_seg_mean_add<<<cdiv(NCL * 32, TB), TB>>>(c, c, m, off_c, csr_c, NCL);

    // ---- l1 clique conv ----
    k_gemmPQ<<<gemmGridC, 256>>>(c, NCL, cnn2_w + HD * HD * HD, cnn2_b + HD * HD, P, Q);
    k_edge_msg<<<cdiv(NEC * 32, TB), TB>>>(NEC, csrc, cdst,
                                           h + (size_t)(2 * NE + NEC) * HD, P, Q, aggc);
    k_finalize_proj<<<cdiv(NCL * 32, TB), TB>>>(c, c, aggc, deg_cdst,
                                                croot_w + HD * HD, croot_b + HD,
                                                c2n_w + HD * HD, c2n_b + HD,
                                                m, NCL, out + (size_t)NN * HD);
    k_seg_mean_add<<<cdiv(NN * 32, TB), TB>>>(x, out, m, off_n, csr_n, NN);
}

// round 9
// speedup vs baseline: 1.2593x; 1.0787x over previous
#include <cuda_runtime.h>
#include <cuda_fp16.h>
#include <cstdint>

#define NN   25000
#define NE   100000
#define HD   32
#define NCL  8000
#define NA   50000
#define NEC  24000
#define EDIM 8
#define XPAD 40   // padded halves per smem row (conflict-free fragments)

// ---------------- scratch (device globals; zero-initialized at load) -----------
__device__ float  g_x[NN * HD];
__device__ float  g_c[NCL * HD];
__device__ float  g_h[(2 * NE + 2 * NEC) * HD];
__device__ __half g_P[(size_t)NN * HD * HD];      // 51.2 MB
__device__ float  g_Q[NN * HD];
__device__ float  g_aggn[NN * HD];                // kept zero between calls
__device__ float  g_aggc[NCL * HD];               // kept zero between calls
__device__ float  g_m[NN * HD];
__device__ int    g_deg[2 * NN + 2 * NCL];        // [dst | cdst | cid | nid]
__device__ int    g_cur[NN + NCL];
__device__ int    g_off_c[NCL + 1];
__device__ int    g_off_n[NN + 1];
__device__ int    g_csr_c[NA];
__device__ int    g_csr_n[NA];

// ---------------- setup ----------------------------------------------------------
__global__ void k_zero_setup(int* __restrict__ deg, int* __restrict__ cur) {
    int i = blockIdx.x * blockDim.x + threadIdx.x;
    if (i < 2 * NN + 2 * NCL) deg[i] = 0;
    if (i < NN + NCL) cur[i] = 0;
}

__global__ void k_count_all(const int* __restrict__ dst, const int* __restrict__ cdst,
                            const int* __restrict__ nid, const int* __restrict__ cid,
                            int* __restrict__ deg) {
    int i = blockIdx.x * blockDim.x + threadIdx.x;
    if (i < NE) {
        atomicAdd(&deg[dst[i]], 1);
    } else if (i < NE + NEC) {
        atomicAdd(&deg[NN + cdst[i - NE]], 1);
    } else if (i < NE + NEC + NA) {
        int j = i - NE - NEC;
        atomicAdd(&deg[NN + NCL + cid[j]], 1);
        atomicAdd(&deg[NN + 2 * NCL + nid[j]], 1);
    }
}

__global__ void k_scan2(const int* __restrict__ degA, int nA_, int* __restrict__ offA,
                        const int* __restrict__ degB, int nB_, int* __restrict__ offB) {
    const int* deg; int n; int* off;
    if (blockIdx.x == 0) { deg = degA; n = nA_; off = offA; }
    else                 { deg = degB; n = nB_; off = offB; }
    __shared__ int s[1024];
    __shared__ int carry;
    int t = threadIdx.x;
    if (t == 0) { carry = 0; off[0] = 0; }
    __syncthreads();
    for (int base = 0; base < n; base += 1024) {
        int v = (base + t < n) ? deg[base + t] : 0;
        s[t] = v;
        __syncthreads();
        for (int d = 1; d < 1024; d <<= 1) {
            int add = (t >= d) ? s[t - d] : 0;
            __syncthreads();
            s[t] += add;
            __syncthreads();
        }
        if (base + t < n) off[base + t + 1] = carry + s[t];
        __syncthreads();
        if (t == 0) carry += s[1023];
        __syncthreads();
    }
}

__global__ void k_fill_csr(const int* __restrict__ nid, const int* __restrict__ cid,
                           const int* __restrict__ off_c, const int* __restrict__ off_n,
                           int* __restrict__ cur,
                           int* __restrict__ csr_c, int* __restrict__ csr_n) {
    int a = blockIdx.x * blockDim.x + threadIdx.x;
    if (a >= NA) return;
    int nd = nid[a], cl = cid[a];
    int p = atomicAdd(&cur[cl], 1);
    csr_c[off_c[cl] + p] = nd;
    int q = atomicAdd(&cur[NCL + nd], 1);
    csr_n[off_n[nd] + q] = cl;
}

// ---------------- ALL edge MLPs, warp per edge-row ---------------------------------
__global__ void k_edge_mlp_all(const float* __restrict__ ef_n, const float* __restrict__ ef_c,
                               const float* __restrict__ nn1_w, const float* __restrict__ nn1_b,
                               const float* __restrict__ cnn1_w, const float* __restrict__ cnn1_b,
                               float* __restrict__ h) {
    int w = (blockIdx.x * blockDim.x + threadIdx.x) >> 5;
    int lane = threadIdx.x & 31;
    const float* ef; const float* w1; const float* b1; float* ho;
    if (w < 2 * NE) {
        int layer = w / NE, e = w - layer * NE;
        ef = ef_n + (size_t)e * EDIM;
        w1 = nn1_w + layer * EDIM * HD;
        b1 = nn1_b + layer * HD;
        ho = h + (size_t)(layer * NE + e) * HD;
    } else if (w < 2 * NE + 2 * NEC) {
        int w2 = w - 2 * NE;
        int layer = w2 / NEC, e = w2 - layer * NEC;
        ef = ef_c + (size_t)e * EDIM;
        w1 = cnn1_w + layer * EDIM * HD;
        b1 = cnn1_b + layer * HD;
        ho = h + (size_t)(2 * NE + layer * NEC + e) * HD;
    } else return;

    float ev = (lane < EDIM) ? ef[lane] : 0.f;
    float acc = b1[lane];
#pragma unroll
    for (int j = 0; j < EDIM; j++)
        acc += __shfl_sync(0xffffffffu, ev, j) * w1[j * HD + lane];
    ho[lane] = fmaxf(acc, 0.f);
}

// ---------------- P = X @ T via HMMA (fp16 in, fp32 acc, fp16 out) + Q slice ------
// blockIdx.y < 8 : 128x128 P tile; blockIdx.y == 8 : Q rows (fp32, warp per row).
__global__ __launch_bounds__(256, 2)
void k_gemmPQ(const float* __restrict__ X, int nrows,
              const float* __restrict__ w2, const float* __restrict__ b2,
              __half* __restrict__ P, float* __restrict__ Q) {
    int tid  = threadIdx.x;
    int row0 = blockIdx.x * 128;

    if (blockIdx.y == 8) {
        int wp = tid >> 5, lane = tid & 31;
        for (int it = 0; it < 16; it++) {
            int r = row0 + it * 8 + wp;
            if (r >= nrows) return;
            float xv = X[(size_t)r * HD + lane];
            float acc = 0.f;
#pragma unroll
            for (int i = 0; i < HD; i++)
                acc += __shfl_sync(0xffffffffu, xv, i) * b2[i * HD + lane];
            Q[(size_t)r * HD + lane] = acc;
        }
        return;
    }

    __shared__ __half Xs[128 * XPAD];   // [row][k], row-major A
    __shared__ __half Ts[128 * XPAD];   // [n][k],  col-major B (K x N)
    int col0 = blockIdx.y * 128;

    // load X tile -> fp16 (2 threads per row, 16 halves each)
    {
        int r  = tid >> 1;
        int hs = (tid & 1) * 16;
        int row = row0 + r;
        __half* dstp = Xs + r * XPAD + hs;
        if (row < nrows) {
            const float* srcp = X + (size_t)row * HD + hs;
#pragma unroll
            for (int j = 0; j < 16; j += 2)
                *(__half2*)(dstp + j) = __float22half2_rn(*(const float2*)(srcp + j));
        } else {
#pragma unroll
            for (int j = 0; j < 16; j += 2)
                *(__half2*)(dstp + j) = __half2half2(__float2half(0.f));
        }
    }
    // load T tile -> fp16, transposed into [n][k]
    // element (k=i, n=cc): w2[((col0+cc)>>5)*1024 + i*32 + ((col0+cc)&31)]
    {
#pragma unroll
        for (int it = 0; it < 4; it++) {
            int q  = tid + 256 * it;      // 0..1023 float4 loads
            int i  = q >> 5;              // k index 0..31
            int cc = (q & 31) * 4;        // col-in-tile 0..124 step 4 (same kcol)
            int kcol = (col0 + cc) >> 5;
            int o    = (col0 + cc) & 31;
            float4 v = *(const float4*)(w2 + kcol * (HD * HD) + i * HD + o);
            Ts[(cc + 0) * XPAD + i] = __float2half_rn(v.x);
            Ts[(cc + 1) * XPAD + i] = __float2half_rn(v.y);
            Ts[(cc + 2) * XPAD + i] = __float2half_rn(v.z);
            Ts[(cc + 3) * XPAD + i] = __float2half_rn(v.w);
        }
    }
    __syncthreads();

    int warp = tid >> 5, lane = tid & 31;
    int wm = (warp >> 1) * 32;       // warp m offset (4 warps along M)
    int wn = (warp & 1) * 64;        // warp n offset (2 warps along N)
    int g  = lane >> 2;              // groupID 0..7
    int tg = lane & 3;               // thread-in-group 0..3

    float acc[2][8][4];
#pragma unroll
    for (int mt = 0; mt < 2; mt++)
#pragma unroll
        for (int nt = 0; nt < 8; nt++)
#pragma unroll
            for (int j = 0; j < 4; j++) acc[mt][nt][j] = 0.f;

#pragma unroll
    for (int ks = 0; ks < 2; ks++) {
        int k0 = ks * 16;
        unsigned a[2][4];
#pragma unroll
        for (int mt = 0; mt < 2; mt++) {
            int rb = wm + mt * 16;
            a[mt][0] = *(unsigned*)&Xs[(rb + g)     * XPAD + k0 + tg * 2];
            a[mt][1] = *(unsigned*)&Xs[(rb + g + 8) * XPAD + k0 + tg * 2];
            a[mt][2] = *(unsigned*)&Xs[(rb + g)     * XPAD + k0 + tg * 2 + 8];
            a[mt][3] = *(unsigned*)&Xs[(rb + g + 8) * XPAD + k0 + tg * 2 + 8];
        }
#pragma unroll
        for (int nt = 0; nt < 8; nt++) {
            int nb = wn + nt * 8;
            unsigned b0 = *(unsigned*)&Ts[(nb + g) * XPAD + k0 + tg * 2];
            unsigned b1 = *(unsigned*)&Ts[(nb + g) * XPAD + k0 + tg * 2 + 8];
#pragma unroll
            for (int mt = 0; mt < 2; mt++) {
                asm volatile(
                    "mma.sync.aligned.m16n8k16.row.col.f32.f16.f16.f32 "
                    "{%0,%1,%2,%3},{%4,%5,%6,%7},{%8,%9},{%0,%1,%2,%3};"
                    : "+f"(acc[mt][nt][0]), "+f"(acc[mt][nt][1]),
                      "+f"(acc[mt][nt][2]), "+f"(acc[mt][nt][3])
                    : "r"(a[mt][0]), "r"(a[mt][1]), "r"(a[mt][2]), "r"(a[mt][3]),
                      "r"(b0), "r"(b1));
            }
        }
    }

    // store C -> fp16 P
#pragma unroll
    for (int mt = 0; mt < 2; mt++) {
        int r1 = row0 + wm + mt * 16 + g;
        int r2 = r1 + 8;
#pragma unroll
        for (int nt = 0; nt < 8; nt++) {
            int cb = col0 + wn + nt * 8 + tg * 2;
            if (r1 < nrows)
                *(__half2*)(P + (size_t)r1 * (HD * HD) + cb) =
                    __floats2half2_rn(acc[mt][nt][0], acc[mt][nt][1]);
            if (r2 < nrows)
                *(__half2*)(P + (size_t)r2 * (HD * HD) + cb) =
                    __floats2half2_rn(acc[mt][nt][2], acc[mt][nt][3]);
        }
    }
}

// ---------------- per-edge message + scatter-add (fp16 P gather, proven) ----------
__global__ void k_edge_msg(int nE, const int* __restrict__ src, const int* __restrict__ dst,
                           const float* __restrict__ h, const __half* __restrict__ P,
                           const float* __restrict__ Q, float* __restrict__ agg) {
    int e = (blockIdx.x * blockDim.x + threadIdx.x) >> 5;
    int lane = threadIdx.x & 31;
    if (e >= nE) return;
    int s = src[e];
    int d = dst[e];
    float hv = h[(size_t)e * HD + lane];
    const __half* Pr = P + (size_t)s * (HD * HD);
    int kq = lane >> 3;
    int og = lane & 7;

    float a0 = 0.f, a1 = 0.f, a2 = 0.f, a3 = 0.f;
#pragma unroll
    for (int it = 0; it < 8; it++) {
        int k = it * 4 + kq;
        float hk = __shfl_sync(0xffffffffu, hv, k);
        uint2 raw = *(const uint2*)(Pr + k * HD + og * 4);
        float2 f01 = __half22float2(*(__half2*)&raw.x);
        float2 f23 = __half22float2(*(__half2*)&raw.y);
        a0 += hk * f01.x; a1 += hk * f01.y; a2 += hk * f23.x; a3 += hk * f23.y;
    }
#pragma unroll
    for (int m = 8; m <= 16; m <<= 1) {
        a0 += __shfl_xor_sync(0xffffffffu, a0, m);
        a1 += __shfl_xor_sync(0xffffffffu, a1, m);
        a2 += __shfl_xor_sync(0xffffffffu, a2, m);
        a3 += __shfl_xor_sync(0xffffffffu, a3, m);
    }
    if (lane < 8) {
        float4 q = *(const float4*)(Q + (size_t)s * HD + lane * 4);
        float* ag = agg + (size_t)d * HD + lane * 4;
        atomicAdd(ag + 0, a0 + q.x);
        atomicAdd(ag + 1, a1 + q.y);
        atomicAdd(ag + 2, a2 + q.z);
        atomicAdd(ag + 3, a3 + q.w);
    }
}

// ---------------- finalize + project; re-zeros agg after consuming ----------------
__global__ void k_finalize_proj(const float* __restrict__ Xin, float* __restrict__ Xout,
                                float* __restrict__ agg, const int* __restrict__ deg,
                                const float* __restrict__ rw, const float* __restrict__ rb,
                                const float* __restrict__ pw, const float* __restrict__ pb,
                                float* __restrict__ m, int nrows,
                                float* __restrict__ copy_out) {
    __shared__ float Rs[HD][HD], Pw[HD][HD];
    for (int i = threadIdx.x; i < HD * HD; i += blockDim.x) {
        Rs[i >> 5][i & 31] = rw[i];
        Pw[i >> 5][i & 31] = pw[i];
    }
    __syncthreads();

    int r = (blockIdx.x * blockDim.x + threadIdx.x) >> 5;
    int lane = threadIdx.x & 31;
    if (r >= nrows) return;
    float xv = Xin[(size_t)r * HD + lane];
    float av = agg[(size_t)r * HD + lane];
    agg[(size_t)r * HD + lane] = 0.f;
    float acc = rb[lane] + av / fmaxf((float)deg[r], 1.f);
#pragma unroll
    for (int i = 0; i < HD; i++)
        acc += __shfl_sync(0xffffffffu, xv, i) * Rs[i][lane];
    float xn = fmaxf(acc, 0.f);
    Xout[(size_t)r * HD + lane] = xn;
    if (copy_out) copy_out[(size_t)r * HD + lane] = xn;
    float macc = pb[lane];
#pragma unroll
    for (int i = 0; i < HD; i++)
        macc += __shfl_sync(0xffffffffu, xn, i) * Pw[i][lane];
    m[(size_t)r * HD + lane] = macc;
}

// ---------------- CSR gather segment-mean + residual add --------------------------
__global__ void k_seg_mean_add(const float* __restrict__ in, float* __restrict__ outp,
                               const float* __restrict__ m,
                               const int* __restrict__ off, const int* __restrict__ csr,
                               int nrows) {
    int r = (blockIdx.x * blockDim.x + threadIdx.x) >> 5;
    int lane = threadIdx.x & 31;
    if (r >= nrows) return;
    int b = off[r], e2 = off[r + 1];
    float acc = 0.f;
    for (int j = b; j < e2; j++)
        acc += m[(size_t)csr[j] * HD + lane];
    outp[(size_t)r * HD + lane] =
        in[(size_t)r * HD + lane] + acc / fmaxf((float)(e2 - b), 1.f);
}

// ===================================================================================
static inline int cdiv(int a, int b) { return (a + b - 1) / b; }

extern "C" void kernel_launch(void* const* d_in, const int* in_sizes, int n_in,
                              void* d_out, int out_size) {
    const float* node_features   = (const float*)d_in[0];
    const int*   edge_index      = (const int*)d_in[1];
    const float* edge_features   = (const float*)d_in[2];
    const float* clique_features = (const float*)d_in[3];
    const int*   n2c_index       = (const int*)d_in[4];
    const int*   cedge_index     = (const int*)d_in[5];
    const float* cedge_features  = (const float*)d_in[6];
    const float* nn1_w  = (const float*)d_in[7];
    const float* nn1_b  = (const float*)d_in[8];
    const float* nn2_w  = (const float*)d_in[9];
    const float* nn2_b  = (const float*)d_in[10];
    const float* root_w = (const float*)d_in[11];
    const float* root_b = (const float*)d_in[12];
    const float* n2c_w  = (const float*)d_in[13];
    const float* n2c_b  = (const float*)d_in[14];
    const float* cnn1_w = (const float*)d_in[15];
    const float* cnn1_b = (const float*)d_in[16];
    const float* cnn2_w = (const float*)d_in[17];
    const float* cnn2_b = (const float*)d_in[18];
    const float* croot_w = (const float*)d_in[19];
    const float* croot_b = (const float*)d_in[20];
    const float* c2n_w  = (const float*)d_in[21];
    const float* c2n_b  = (const float*)d_in[22];
    float* out = (float*)d_out;

    const int* src  = edge_index;
    const int* dst  = edge_index + NE;
    const int* nid  = n2c_index;
    const int* cid  = n2c_index + NA;
    const int* csrc = cedge_index;
    const int* cdst = cedge_index + NEC;

    float *x, *c, *h, *Q, *aggn, *aggc, *m;
    __half* P;
    int *deg, *cur, *off_c, *off_n, *csr_c, *csr_n;
    cudaGetSymbolAddress((void**)&x, g_x);
    cudaGetSymbolAddress((void**)&c, g_c);
    cudaGetSymbolAddress((void**)&h, g_h);
    cudaGetSymbolAddress((void**)&P, g_P);
    cudaGetSymbolAddress((void**)&Q, g_Q);
    cudaGetSymbolAddress((void**)&aggn, g_aggn);
    cudaGetSymbolAddress((void**)&aggc, g_aggc);
    cudaGetSymbolAddress((void**)&m, g_m);
    cudaGetSymbolAddress((void**)&deg, g_deg);
    cudaGetSymbolAddress((void**)&cur, g_cur);
    cudaGetSymbolAddress((void**)&off_c, g_off_c);
    cudaGetSymbolAddress((void**)&off_n, g_off_n);
    cudaGetSymbolAddress((void**)&csr_c, g_csr_c);
    cudaGetSymbolAddress((void**)&csr_n, g_csr_n);
    const int* deg_dst  = deg;
    const int* deg_cdst = deg + NN;
    const int* deg_cid  = deg + NN + NCL;
    const int* deg_nid  = deg + NN + 2 * NCL;

    const int TB = 256;
    dim3 gemmGridN(cdiv(NN, 128), 9);   // y==8 is the Q slice
    dim3 gemmGridC(cdiv(NCL, 128), 9);

    // ---- launch order: gemmPQ is launch #4 -> profiled by ncu ----
    k_edge_mlp_all<<<cdiv((2 * NE + 2 * NEC) * 32, TB), TB>>>(
        edge_features, cedge_features, nn1_w, nn1_b, cnn1_w, cnn1_b, h);
    k_zero_setup<<<cdiv(2 * NN + 2 * NCL, TB), TB>>>(deg, cur);
    k_count_all<<<cdiv(NE + NEC + NA, TB), TB>>>(dst, cdst, nid, cid, deg);
    // 4: node gemm l0 (HMMA)  <-- PROFILED
    k_gemmPQ<<<gemmGridN, 256>>>(node_features, NN, nn2_w, nn2_b, P, Q);
    k_edge_msg<<<cdiv(NE * 32, TB), TB>>>(NE, src, dst, h, P, Q, aggn);
    k_scan2<<<2, 1024>>>(deg_cid, NCL, off_c, deg_nid, NN, off_n);
    k_fill_csr<<<cdiv(NA, TB), TB>>>(nid, cid, off_c, off_n, cur, csr_c, csr_n);
    k_finalize_proj<<<cdiv(NN * 32, TB), TB>>>(node_features, x, aggn, deg_dst,
                                               root_w, root_b, n2c_w, n2c_b,
                                               m, NN, nullptr);
    k_seg_mean_add<<<cdiv(NCL * 32, TB), TB>>>(clique_features, c, m, off_c, csr_c, NCL);

    // ---- l0 clique conv ----
    k_gemmPQ<<<gemmGridC, 256>>>(c, NCL, cnn2_w, cnn2_b, P, Q);
    k_edge_msg<<<cdiv(NEC * 32, TB), TB>>>(NEC, csrc, cdst, h + (size_t)2 * NE * HD, P, Q, aggc);
    k_finalize_proj<<<cdiv(NCL * 32, TB), TB>>>(c, c, aggc, deg_cdst,
                                                croot_w, croot_b, c2n_w, c2n_b,
                                                m, NCL, nullptr);
    k_seg_mean_add<<<cdiv(NN * 32, TB), TB>>>(x, x, m, off_n, csr_n, NN);

    // ---- l1 node conv ----
    k_gemmPQ<<<gemmGridN, 256>>>(x, NN, nn2_w + HD * HD * HD, nn2_b + HD * HD, P, Q);
    k_edge_msg<<<cdiv(NE * 32, TB), TB>>>(NE, src, dst, h + (size_t)NE * HD, P, Q, aggn);
    k_finalize_proj<<<cdiv(NN * 32, TB), TB>>>(x, x, aggn, deg_dst,
                                               root_w + HD * HD, root_b + HD,
                                               n2c_w + HD * HD, n2c_b + HD,
                                               m, NN, nullptr);
    k_seg_mean_add<<<cdiv(NCL * 32, TB), TB>>>(c, c, m, off_c, csr_c, NCL);

    // ---- l1 clique conv ----
    k_gemmPQ<<<gemmGridC, 256>>>(c, NCL, cnn2_w + HD * HD * HD, cnn2_b + HD * HD, P, Q);
    k_edge_msg<<<cdiv(NEC * 32, TB), TB>>>(NEC, csrc, cdst,
                                           h + (size_t)(2 * NE + NEC) * HD, P, Q, aggc);
    k_finalize_proj<<<cdiv(NCL * 32, TB), TB>>>(c, c, aggc, deg_cdst,
                                                croot_w + HD * HD, croot_b + HD,
                                                c2n_w + HD * HD, c2n_b + HD,
                                                m, NCL, out + (size_t)NN * HD);
    k_seg_mean_add<<<cdiv(NN * 32, TB), TB>>>(x, out, m, off_n, csr_n, NN);
}

// round 10
// speedup vs baseline: 1.3830x; 1.0982x over previous
#include <cuda_runtime.h>
#include <cuda_fp16.h>
#include <cstdint>

#define NN   25000
#define NE   100000
#define HD   32
#define NCL  8000
#define NA   50000
#define NEC  24000
#define EDIM 8
#define XPAD 40   // padded halves per smem row (conflict-free fragments)

// ---------------- scratch (device globals; zero-initialized at load) -----------
__device__ float  g_x[NN * HD];
__device__ float  g_c[NCL * HD];
__device__ float  g_h[(2 * NE + 2 * NEC) * HD];
__device__ __half g_P[(size_t)NN * HD * HD];      // 51.2 MB
__device__ float  g_Q[NN * HD];
__device__ float  g_aggn[NN * HD];                // kept zero between calls
__device__ float  g_aggc[NCL * HD];               // kept zero between calls
__device__ float  g_m[NN * HD];
__device__ int    g_deg[2 * NN + 2 * NCL];        // [dst | cdst | cid | nid]
__device__ int    g_cur[NN + NCL];
__device__ int    g_off_c[NCL + 1];
__device__ int    g_off_n[NN + 1];
__device__ int    g_csr_c[NA];
__device__ int    g_csr_n[NA];

// ---------------- setup ----------------------------------------------------------
__global__ void k_zero_setup(int* __restrict__ deg, int* __restrict__ cur) {
    int i = blockIdx.x * blockDim.x + threadIdx.x;
    if (i < 2 * NN + 2 * NCL) deg[i] = 0;
    if (i < NN + NCL) cur[i] = 0;
}

__global__ void k_count_all(const int* __restrict__ dst, const int* __restrict__ cdst,
                            const int* __restrict__ nid, const int* __restrict__ cid,
                            int* __restrict__ deg) {
    int i = blockIdx.x * blockDim.x + threadIdx.x;
    if (i < NE) {
        atomicAdd(&deg[dst[i]], 1);
    } else if (i < NE + NEC) {
        atomicAdd(&deg[NN + cdst[i - NE]], 1);
    } else if (i < NE + NEC + NA) {
        int j = i - NE - NEC;
        atomicAdd(&deg[NN + NCL + cid[j]], 1);
        atomicAdd(&deg[NN + 2 * NCL + nid[j]], 1);
    }
}

__global__ void k_scan2(const int* __restrict__ degA, int nA_, int* __restrict__ offA,
                        const int* __restrict__ degB, int nB_, int* __restrict__ offB) {
    const int* deg; int n; int* off;
    if (blockIdx.x == 0) { deg = degA; n = nA_; off = offA; }
    else                 { deg = degB; n = nB_; off = offB; }
    __shared__ int s[1024];
    __shared__ int carry;
    int t = threadIdx.x;
    if (t == 0) { carry = 0; off[0] = 0; }
    __syncthreads();
    for (int base = 0; base < n; base += 1024) {
        int v = (base + t < n) ? deg[base + t] : 0;
        s[t] = v;
        __syncthreads();
        for (int d = 1; d < 1024; d <<= 1) {
            int add = (t >= d) ? s[t - d] : 0;
            __syncthreads();
            s[t] += add;
            __syncthreads();
        }
        if (base + t < n) off[base + t + 1] = carry + s[t];
        __syncthreads();
        if (t == 0) carry += s[1023];
        __syncthreads();
    }
}

__global__ void k_fill_csr(const int* __restrict__ nid, const int* __restrict__ cid,
                           const int* __restrict__ off_c, const int* __restrict__ off_n,
                           int* __restrict__ cur,
                           int* __restrict__ csr_c, int* __restrict__ csr_n) {
    int a = blockIdx.x * blockDim.x + threadIdx.x;
    if (a >= NA) return;
    int nd = nid[a], cl = cid[a];
    int p = atomicAdd(&cur[cl], 1);
    csr_c[off_c[cl] + p] = nd;
    int q = atomicAdd(&cur[NCL + nd], 1);
    csr_n[off_n[nd] + q] = cl;
}

// ---------------- ALL edge MLPs, warp per edge-row ---------------------------------
__global__ void k_edge_mlp_all(const float* __restrict__ ef_n, const float* __restrict__ ef_c,
                               const float* __restrict__ nn1_w, const float* __restrict__ nn1_b,
                               const float* __restrict__ cnn1_w, const float* __restrict__ cnn1_b,
                               float* __restrict__ h) {
    int w = (blockIdx.x * blockDim.x + threadIdx.x) >> 5;
    int lane = threadIdx.x & 31;
    const float* ef; const float* w1; const float* b1; float* ho;
    if (w < 2 * NE) {
        int layer = w / NE, e = w - layer * NE;
        ef = ef_n + (size_t)e * EDIM;
        w1 = nn1_w + layer * EDIM * HD;
        b1 = nn1_b + layer * HD;
        ho = h + (size_t)(layer * NE + e) * HD;
    } else if (w < 2 * NE + 2 * NEC) {
        int w2 = w - 2 * NE;
        int layer = w2 / NEC, e = w2 - layer * NEC;
        ef = ef_c + (size_t)e * EDIM;
        w1 = cnn1_w + layer * EDIM * HD;
        b1 = cnn1_b + layer * HD;
        ho = h + (size_t)(2 * NE + layer * NEC + e) * HD;
    } else return;

    float ev = (lane < EDIM) ? ef[lane] : 0.f;
    float acc = b1[lane];
#pragma unroll
    for (int j = 0; j < EDIM; j++)
        acc += __shfl_sync(0xffffffffu, ev, j) * w1[j * HD + lane];
    ho[lane] = fmaxf(acc, 0.f);
}

// ---------------- P = X @ T via HMMA + ldmatrix + coalesced stores + Q slice -------
// blockIdx.y < 8 : 128x128 P tile; blockIdx.y == 8 : Q rows (fp32, warp per row).
// B smem columns are PERMUTED: mma n-position ws*64 + nt*8 + tg*2 + j holds global
// column ws*64 + tg*16 + nt*2 + j, so each thread's outputs are 16 contiguous halves.
__global__ __launch_bounds__(256, 2)
void k_gemmPQ(const float* __restrict__ X, int nrows,
              const float* __restrict__ w2, const float* __restrict__ b2,
              __half* __restrict__ P, float* __restrict__ Q) {
    int tid  = threadIdx.x;
    int row0 = blockIdx.x * 128;

    if (blockIdx.y == 8) {
        int wp = tid >> 5, lane = tid & 31;
        for (int it = 0; it < 16; it++) {
            int r = row0 + it * 8 + wp;
            if (r >= nrows) return;
            float xv = X[(size_t)r * HD + lane];
            float acc = 0.f;
#pragma unroll
            for (int i = 0; i < HD; i++)
                acc += __shfl_sync(0xffffffffu, xv, i) * b2[i * HD + lane];
            Q[(size_t)r * HD + lane] = acc;
        }
        return;
    }

    __shared__ __half Xs[128 * XPAD];   // [row][k]
    __shared__ __half Ts[128 * XPAD];   // [n-pos][k], column-permuted
    int col0 = blockIdx.y * 128;

    // load X tile -> fp16 (2 threads per row, 16 halves each)
    {
        int r  = tid >> 1;
        int hs = (tid & 1) * 16;
        int row = row0 + r;
        __half* dstp = Xs + r * XPAD + hs;
        if (row < nrows) {
            const float* srcp = X + (size_t)row * HD + hs;
#pragma unroll
            for (int j = 0; j < 16; j += 2)
                *(__half2*)(dstp + j) = __float22half2_rn(*(const float2*)(srcp + j));
        } else {
#pragma unroll
            for (int j = 0; j < 16; j += 2)
                *(__half2*)(dstp + j) = __half2half2(__float2half(0.f));
        }
    }
    // load T tile -> fp16 with column permutation.
    // logical T element (k=i, global col C=col0+c): w2[(C>>5)*1024 + i*32 + (C&31)]
    // smem position for global offset c: ws*64 + nt*8 + tg*2 + j
    //   where ws=c>>6, tg=(c&63)>>4, nt=((c&15)>>1), j=c&1
    {
#pragma unroll
        for (int it = 0; it < 4; it++) {
            int q  = tid + 256 * it;      // 0..1023
            int i  = q >> 5;              // k index 0..31
            int c4 = (q & 31) * 4;        // global col offset 0..124 step 4
            int kcol = (col0 + c4) >> 5;
            int o    = (col0 + c4) & 31;
            float4 v = *(const float4*)(w2 + kcol * (HD * HD) + i * HD + o);
            float vv[4] = {v.x, v.y, v.z, v.w};
#pragma unroll
            for (int j4 = 0; j4 < 4; j4++) {
                int c = c4 + j4;
                int ws = c >> 6, within = c & 63;
                int tg = within >> 4, rem = within & 15;
                int pos = ws * 64 + (rem >> 1) * 8 + tg * 2 + (rem & 1);
                Ts[pos * XPAD + i] = __float2half_rn(vv[j4]);
            }
        }
    }
    __syncthreads();

    int warp = tid >> 5, lane = tid & 31;
    int wm = (warp >> 1) * 32;       // warp m offset (4 warps along M)
    int wn = (warp & 1) * 64;        // warp n offset (2 warps along N)
    int g  = lane >> 2;              // groupID 0..7
    int tg = lane & 3;               // thread-in-group 0..3

    unsigned xs_base = (unsigned)__cvta_generic_to_shared(Xs);
    unsigned ts_base = (unsigned)__cvta_generic_to_shared(Ts);

    float acc[2][8][4];
#pragma unroll
    for (int mt = 0; mt < 2; mt++)
#pragma unroll
        for (int nt = 0; nt < 8; nt++)
#pragma unroll
            for (int j = 0; j < 4; j++) acc[mt][nt][j] = 0.f;

#pragma unroll
    for (int ks = 0; ks < 2; ks++) {
        int k0 = ks * 16;
        // A fragments via ldmatrix.x4 (one per 16-row mt tile)
        unsigned a[2][4];
#pragma unroll
        for (int mt = 0; mt < 2; mt++) {
            int lrow = wm + mt * 16 + (lane & 15);
            int lk   = k0 + ((lane >> 4) << 3);
            unsigned addr = xs_base + (unsigned)(lrow * XPAD + lk) * 2u;
            asm volatile("ldmatrix.sync.aligned.m8n8.x4.shared.b16 {%0,%1,%2,%3}, [%4];"
                         : "=r"(a[mt][0]), "=r"(a[mt][1]), "=r"(a[mt][2]), "=r"(a[mt][3])
                         : "r"(addr));
        }
        // B fragments via ldmatrix.x4 (two n-tiles per instruction)
        unsigned b[8][2];
#pragma unroll
        for (int np = 0; np < 4; np++) {
            int nb = wn + np * 16;
            int quarter = lane >> 3;
            int nrow = nb + ((quarter >> 1) << 3) + (lane & 7);
            int kk   = k0 + ((quarter & 1) << 3);
            unsigned addr = ts_base + (unsigned)(nrow * XPAD + kk) * 2u;
            asm volatile("ldmatrix.sync.aligned.m8n8.x4.shared.b16 {%0,%1,%2,%3}, [%4];"
                         : "=r"(b[np * 2][0]), "=r"(b[np * 2][1]),
                           "=r"(b[np * 2 + 1][0]), "=r"(b[np * 2 + 1][1])
                         : "r"(addr));
        }
#pragma unroll
        for (int nt = 0; nt < 8; nt++) {
#pragma unroll
            for (int mt = 0; mt < 2; mt++) {
                asm volatile(
                    "mma.sync.aligned.m16n8k16.row.col.f32.f16.f16.f32 "
                    "{%0,%1,%2,%3},{%4,%5,%6,%7},{%8,%9},{%0,%1,%2,%3};"
                    : "+f"(acc[mt][nt][0]), "+f"(acc[mt][nt][1]),
                      "+f"(acc[mt][nt][2]), "+f"(acc[mt][nt][3])
                    : "r"(a[mt][0]), "r"(a[mt][1]), "r"(a[mt][2]), "r"(a[mt][3]),
                      "r"(b[nt][0]), "r"(b[nt][1]));
            }
        }
    }

    // store: thread (g,tg) owns 16 contiguous global halves per row
    int cb0 = col0 + wn + tg * 16;
#pragma unroll
    for (int mt = 0; mt < 2; mt++) {
        int r1 = row0 + wm + mt * 16 + g;
        int r2 = r1 + 8;
        unsigned lo[8], hi[8];
#pragma unroll
        for (int nt = 0; nt < 8; nt++) {
            __half2 h1 = __floats2half2_rn(acc[mt][nt][0], acc[mt][nt][1]);
            __half2 h2 = __floats2half2_rn(acc[mt][nt][2], acc[mt][nt][3]);
            lo[nt] = *(unsigned*)&h1;
            hi[nt] = *(unsigned*)&h2;
        }
        if (r1 < nrows) {
            uint4* dp = (uint4*)(P + (size_t)r1 * (HD * HD) + cb0);
            dp[0] = make_uint4(lo[0], lo[1], lo[2], lo[3]);
            dp[1] = make_uint4(lo[4], lo[5], lo[6], lo[7]);
        }
        if (r2 < nrows) {
            uint4* dp = (uint4*)(P + (size_t)r2 * (HD * HD) + cb0);
            dp[0] = make_uint4(hi[0], hi[1], hi[2], hi[3]);
            dp[1] = make_uint4(hi[4], hi[5], hi[6], hi[7]);
        }
    }
}

// ---------------- per-edge message + scatter-add (fp16 P gather, proven) ----------
__global__ void k_edge_msg(int nE, const int* __restrict__ src, const int* __restrict__ dst,
                           const float* __restrict__ h, const __half* __restrict__ P,
                           const float* __restrict__ Q, float* __restrict__ agg) {
    int e = (blockIdx.x * blockDim.x + threadIdx.x) >> 5;
    int lane = threadIdx.x & 31;
    if (e >= nE) return;
    int s = src[e];
    int d = dst[e];
    float hv = h[(size_t)e * HD + lane];
    const __half* Pr = P + (size_t)s * (HD * HD);
    int kq = lane >> 3;
    int og = lane & 7;

    float a0 = 0.f, a1 = 0.f, a2 = 0.f, a3 = 0.f;
#pragma unroll
    for (int it = 0; it < 8; it++) {
        int k = it * 4 + kq;
        float hk = __shfl_sync(0xffffffffu, hv, k);
        uint2 raw = *(const uint2*)(Pr + k * HD + og * 4);
        float2 f01 = __half22float2(*(__half2*)&raw.x);
        float2 f23 = __half22float2(*(__half2*)&raw.y);
        a0 += hk * f01.x; a1 += hk * f01.y; a2 += hk * f23.x; a3 += hk * f23.y;
    }
#pragma unroll
    for (int m = 8; m <= 16; m <<= 1) {
        a0 += __shfl_xor_sync(0xffffffffu, a0, m);
        a1 += __shfl_xor_sync(0xffffffffu, a1, m);
        a2 += __shfl_xor_sync(0xffffffffu, a2, m);
        a3 += __shfl_xor_sync(0xffffffffu, a3, m);
    }
    if (lane < 8) {
        float4 q = *(const float4*)(Q + (size_t)s * HD + lane * 4);
        float* ag = agg + (size_t)d * HD + lane * 4;
        atomicAdd(ag + 0, a0 + q.x);
        atomicAdd(ag + 1, a1 + q.y);
        atomicAdd(ag + 2, a2 + q.z);
        atomicAdd(ag + 3, a3 + q.w);
    }
}

// ---------------- finalize + project; re-zeros agg after consuming ----------------
__global__ void k_finalize_proj(const float* __restrict__ Xin, float* __restrict__ Xout,
                                float* __restrict__ agg, const int* __restrict__ deg,
                                const float* __restrict__ rw, const float* __restrict__ rb,
                                const float* __restrict__ pw, const float* __restrict__ pb,
                                float* __restrict__ m, int nrows,
                                float* __restrict__ copy_out) {
    __shared__ float Rs[HD][HD], Pw[HD][HD];
    for (int i = threadIdx.x; i < HD * HD; i += blockDim.x) {
        Rs[i >> 5][i & 31] = rw[i];
        Pw[i >> 5][i & 31] = pw[i];
    }
    __syncthreads();

    int r = (blockIdx.x * blockDim.x + threadIdx.x) >> 5;
    int lane = threadIdx.x & 31;
    if (r >= nrows) return;
    float xv = Xin[(size_t)r * HD + lane];
    float av = agg[(size_t)r * HD + lane];
    agg[(size_t)r * HD + lane] = 0.f;
    float acc = rb[lane] + av / fmaxf((float)deg[r], 1.f);
#pragma unroll
    for (int i = 0; i < HD; i++)
        acc += __shfl_sync(0xffffffffu, xv, i) * Rs[i][lane];
    float xn = fmaxf(acc, 0.f);
    Xout[(size_t)r * HD + lane] = xn;
    if (copy_out) copy_out[(size_t)r * HD + lane] = xn;
    float macc = pb[lane];
#pragma unroll
    for (int i = 0; i < HD; i++)
        macc += __shfl_sync(0xffffffffu, xn, i) * Pw[i][lane];
    m[(size_t)r * HD + lane] = macc;
}

// ---------------- CSR gather segment-mean + residual add --------------------------
__global__ void k_seg_mean_add(const float* __restrict__ in, float* __restrict__ outp,
                               const float* __restrict__ m,
                               const int* __restrict__ off, const int* __restrict__ csr,
                               int nrows) {
    int r = (blockIdx.x * blockDim.x + threadIdx.x) >> 5;
    int lane = threadIdx.x & 31;
    if (r >= nrows) return;
    int b = off[r], e2 = off[r + 1];
    float acc = 0.f;
    for (int j = b; j < e2; j++)
        acc += m[(size_t)csr[j] * HD + lane];
    outp[(size_t)r * HD + lane] =
        in[(size_t)r * HD + lane] + acc / fmaxf((float)(e2 - b), 1.f);
}

// ===================================================================================
static inline int cdiv(int a, int b) { return (a + b - 1) / b; }

extern "C" void kernel_launch(void* const* d_in, const int* in_sizes, int n_in,
                              void* d_out, int out_size) {
    const float* node_features   = (const float*)d_in[0];
    const int*   edge_index      = (const int*)d_in[1];
    const float* edge_features   = (const float*)d_in[2];
    const float* clique_features = (const float*)d_in[3];
    const int*   n2c_index       = (const int*)d_in[4];
    const int*   cedge_index     = (const int*)d_in[5];
    const float* cedge_features  = (const float*)d_in[6];
    const float* nn1_w  = (const float*)d_in[7];
    const float* nn1_b  = (const float*)d_in[8];
    const float* nn2_w  = (const float*)d_in[9];
    const float* nn2_b  = (const float*)d_in[10];
    const float* root_w = (const float*)d_in[11];
    const float* root_b = (const float*)d_in[12];
    const float* n2c_w  = (const float*)d_in[13];
    const float* n2c_b  = (const float*)d_in[14];
    const float* cnn1_w = (const float*)d_in[15];
    const float* cnn1_b = (const float*)d_in[16];
    const float* cnn2_w = (const float*)d_in[17];
    const float* cnn2_b = (const float*)d_in[18];
    const float* croot_w = (const float*)d_in[19];
    const float* croot_b = (const float*)d_in[20];
    const float* c2n_w  = (const float*)d_in[21];
    const float* c2n_b  = (const float*)d_in[22];
    float* out = (float*)d_out;

    const int* src  = edge_index;
    const int* dst  = edge_index + NE;
    const int* nid  = n2c_index;
    const int* cid  = n2c_index + NA;
    const int* csrc = cedge_index;
    const int* cdst = cedge_index + NEC;

    float *x, *c, *h, *Q, *aggn, *aggc, *m;
    __half* P;
    int *deg, *cur, *off_c, *off_n, *csr_c, *csr_n;
    cudaGetSymbolAddress((void**)&x, g_x);
    cudaGetSymbolAddress((void**)&c, g_c);
    cudaGetSymbolAddress((void**)&h, g_h);
    cudaGetSymbolAddress((void**)&P, g_P);
    cudaGetSymbolAddress((void**)&Q, g_Q);
    cudaGetSymbolAddress((void**)&aggn, g_aggn);
    cudaGetSymbolAddress((void**)&aggc, g_aggc);
    cudaGetSymbolAddress((void**)&m, g_m);
    cudaGetSymbolAddress((void**)&deg, g_deg);
    cudaGetSymbolAddress((void**)&cur, g_cur);
    cudaGetSymbolAddress((void**)&off_c, g_off_c);
    cudaGetSymbolAddress((void**)&off_n, g_off_n);
    cudaGetSymbolAddress((void**)&csr_c, g_csr_c);
    cudaGetSymbolAddress((void**)&csr_n, g_csr_n);
    const int* deg_dst  = deg;
    const int* deg_cdst = deg + NN;
    const int* deg_cid  = deg + NN + NCL;
    const int* deg_nid  = deg + NN + 2 * NCL;

    const int TB = 256;
    dim3 gemmGridN(cdiv(NN, 128), 9);   // y==8 is the Q slice
    dim3 gemmGridC(cdiv(NCL, 128), 9);

    // ---- launch order: gemmPQ is launch #4 -> profiled by ncu ----
    k_edge_mlp_all<<<cdiv((2 * NE + 2 * NEC) * 32, TB), TB>>>(
        edge_features, cedge_features, nn1_w, nn1_b, cnn1_w, cnn1_b, h);
    k_zero_setup<<<cdiv(2 * NN + 2 * NCL, TB), TB>>>(deg, cur);
    k_count_all<<<cdiv(NE + NEC + NA, TB), TB>>>(dst, cdst, nid, cid, deg);
    // 4: node gemm l0 (HMMA + ldmatrix)  <-- PROFILED
    k_gemmPQ<<<gemmGridN, 256>>>(node_features, NN, nn2_w, nn2_b, P, Q);
    k_edge_msg<<<cdiv(NE * 32, TB), TB>>>(NE, src, dst, h, P, Q, aggn);
    k_scan2<<<2, 1024>>>(deg_cid, NCL, off_c, deg_nid, NN, off_n);
    k_fill_csr<<<cdiv(NA, TB), TB>>>(nid, cid, off_c, off_n, cur, csr_c, csr_n);
    k_finalize_proj<<<cdiv(NN * 32, TB), TB>>>(node_features, x, aggn, deg_dst,
                                               root_w, root_b, n2c_w, n2c_b,
                                               m, NN, nullptr);
    k_seg_mean_add<<<cdiv(NCL * 32, TB), TB>>>(clique_features, c, m, off_c, csr_c, NCL);

    // ---- l0 clique conv ----
    k_gemmPQ<<<gemmGridC, 256>>>(c, NCL, cnn2_w, cnn2_b, P, Q);
    k_edge_msg<<<cdiv(NEC * 32, TB), TB>>>(NEC, csrc, cdst, h + (size_t)2 * NE * HD, P, Q, aggc);
    k_finalize_proj<<<cdiv(NCL * 32, TB), TB>>>(c, c, aggc, deg_cdst,
                                                croot_w, croot_b, c2n_w, c2n_b,
                                                m, NCL, nullptr);
    k_seg_mean_add<<<cdiv(NN * 32, TB), TB>>>(x, x, m, off_n, csr_n, NN);

    // ---- l1 node conv ----
    k_gemmPQ<<<gemmGridN, 256>>>(x, NN, nn2_w + HD * HD * HD, nn2_b + HD * HD, P, Q);
    k_edge_msg<<<cdiv(NE * 32, TB), TB>>>(NE, src, dst, h + (size_t)NE * HD, P, Q, aggn);
    k_finalize_proj<<<cdiv(NN * 32, TB), TB>>>(x, x, aggn, deg_dst,
                                               root_w + HD * HD, root_b + HD,
                                               n2c_w + HD * HD, n2c_b + HD,
                                               m, NN, nullptr);
    k_seg_mean_add<<<cdiv(NCL * 32, TB), TB>>>(c, c, m, off_c, csr_c, NCL);

    // ---- l1 clique conv ----
    k_gemmPQ<<<gemmGridC, 256>>>(c, NCL, cnn2_w + HD * HD * HD, cnn2_b + HD * HD, P, Q);
    k_edge_msg<<<cdiv(NEC * 32, TB), TB>>>(NEC, csrc, cdst,
                                           h + (size_t)(2 * NE + NEC) * HD, P, Q, aggc);
    k_finalize_proj<<<cdiv(NCL * 32, TB), TB>>>(c, c, aggc, deg_cdst,
                                                croot_w + HD * HD, croot_b + HD,
                                                c2n_w + HD * HD, c2n_b + HD,
                                                m, NCL, out + (size_t)NN * HD);
    k_seg_mean_add<<<cdiv(NN * 32, TB), TB>>>(x, out, m, off_n, csr_n, NN);
}

// round 12
// speedup vs baseline: 1.5486x; 1.1197x over previous
#include <cuda_runtime.h>
#include <cuda_fp16.h>
#include <cstdint>

#define NN   25000
#define NE   100000
#define HD   32
#define NCL  8000
#define NA   50000
#define NEC  24000
#define EDIM 8
#define XPAD 40   // padded halves per smem row (conflict-free ldmatrix)

#define TG_TILE   (128 * XPAD)            // halves per column tile
#define TG_CONV   (8 * TG_TILE)           // halves per conv matrix (40960)
#define SMEM_GEMM ((128 * XPAD + 8 * TG_TILE) * 2)   // 92160 bytes

// ---------------- scratch (device globals; zero-initialized at load) -----------
__device__ float  g_x[NN * HD];
__device__ float  g_c[NCL * HD];
__device__ float  g_h[(2 * NE + 2 * NEC) * HD];
__device__ __half g_P[(size_t)NN * HD * HD];      // 51.2 MB
__device__ __half g_T[4 * TG_CONV];               // 4 convs, padded+permuted fp16
__device__ float  g_Q[NN * HD];
__device__ float  g_aggn[NN * HD];                // kept zero between calls
__device__ float  g_aggc[NCL * HD];               // kept zero between calls
__device__ float  g_m[NN * HD];
__device__ int    g_deg[2 * NN + 2 * NCL];        // [dst | cdst | cid | nid]
__device__ int    g_cur[NN + NCL];
__device__ int    g_off_c[NCL + 1];
__device__ int    g_off_n[NN + 1];
__device__ int    g_csr_c[NA];
__device__ int    g_csr_n[NA];

// ---------------- setup ----------------------------------------------------------
__global__ void k_zero_setup(int* __restrict__ deg, int* __restrict__ cur) {
    int i = blockIdx.x * blockDim.x + threadIdx.x;
    if (i < 2 * NN + 2 * NCL) deg[i] = 0;
    if (i < NN + NCL) cur[i] = 0;
}

__global__ void k_count_all(const int* __restrict__ dst, const int* __restrict__ cdst,
                            const int* __restrict__ nid, const int* __restrict__ cid,
                            int* __restrict__ deg) {
    int i = blockIdx.x * blockDim.x + threadIdx.x;
    if (i < NE) {
        atomicAdd(&deg[dst[i]], 1);
    } else if (i < NE + NEC) {
        atomicAdd(&deg[NN + cdst[i - NE]], 1);
    } else if (i < NE + NEC + NA) {
        int j = i - NE - NEC;
        atomicAdd(&deg[NN + NCL + cid[j]], 1);
        atomicAdd(&deg[NN + 2 * NCL + nid[j]], 1);
    }
}

__global__ void k_scan2(const int* __restrict__ degA, int nA_, int* __restrict__ offA,
                        const int* __restrict__ degB, int nB_, int* __restrict__ offB) {
    const int* deg; int n; int* off;
    if (blockIdx.x == 0) { deg = degA; n = nA_; off = offA; }
    else                 { deg = degB; n = nB_; off = offB; }
    __shared__ int s[1024];
    __shared__ int carry;
    int t = threadIdx.x;
    if (t == 0) { carry = 0; off[0] = 0; }
    __syncthreads();
    for (int base = 0; base < n; base += 1024) {
        int v = (base + t < n) ? deg[base + t] : 0;
        s[t] = v;
        __syncthreads();
        for (int d = 1; d < 1024; d <<= 1) {
            int add = (t >= d) ? s[t - d] : 0;
            __syncthreads();
            s[t] += add;
            __syncthreads();
        }
        if (base + t < n) off[base + t + 1] = carry + s[t];
        __syncthreads();
        if (t == 0) carry += s[1023];
        __syncthreads();
    }
}

__global__ void k_fill_csr(const int* __restrict__ nid, const int* __restrict__ cid,
                           const int* __restrict__ off_c, const int* __restrict__ off_n,
                           int* __restrict__ cur,
                           int* __restrict__ csr_c, int* __restrict__ csr_n) {
    int a = blockIdx.x * blockDim.x + threadIdx.x;
    if (a >= NA) return;
    int nd = nid[a], cl = cid[a];
    int p = atomicAdd(&cur[cl], 1);
    csr_c[off_c[cl] + p] = nd;
    int q = atomicAdd(&cur[NCL + nd], 1);
    csr_n[off_n[nd] + q] = cl;
}

// ---------------- convert all 4 w2 matrices to padded+permuted fp16 ---------------
// Tg[((j*8+ct)*128+pos)*XPAD+i] = half(w2_j[(C>>5)*1024 + i*32 + (C&31)]),
// C = ct*128 + c, c = invperm(pos): ws=pos>>6, w=pos&63, nt=w>>3, lo=w&7,
// tg=lo>>1, j0=lo&1, c = ws*64 + tg*16 + nt*2 + j0.
__global__ void k_convT(const float* __restrict__ nn2_w, const float* __restrict__ cnn2_w,
                        __half* __restrict__ Tg) {
    int t = blockIdx.x * blockDim.x + threadIdx.x;
    if (t >= 4 * 8 * 128 * 32) return;
    int i   = t & 31;
    int pos = (t >> 5) & 127;
    int ct  = (t >> 12) & 7;
    int j   = t >> 15;
    const float* w2 = (j < 2 ? nn2_w : cnn2_w) + (j & 1) * (HD * HD * HD);
    int ws = pos >> 6, w = pos & 63, nt = w >> 3, lo = w & 7;
    int tg = lo >> 1, j0 = lo & 1;
    int c  = ws * 64 + tg * 16 + nt * 2 + j0;
    int C  = ct * 128 + c;
    float v = w2[(C >> 5) * (HD * HD) + i * HD + (C & 31)];
    Tg[((size_t)(j * 8 + ct) * 128 + pos) * XPAD + i] = __float2half_rn(v);
}

// ---------------- ALL edge MLPs, warp per edge-row ---------------------------------
__global__ void k_edge_mlp_all(const float* __restrict__ ef_n, const float* __restrict__ ef_c,
                               const float* __restrict__ nn1_w, const float* __restrict__ nn1_b,
                               const float* __restrict__ cnn1_w, const float* __restrict__ cnn1_b,
                               float* __restrict__ h) {
    int w = (blockIdx.x * blockDim.x + threadIdx.x) >> 5;
    int lane = threadIdx.x & 31;
    const float* ef; const float* w1; const float* b1; float* ho;
    if (w < 2 * NE) {
        int layer = w / NE, e = w - layer * NE;
        ef = ef_n + (size_t)e * EDIM;
        w1 = nn1_w + layer * EDIM * HD;
        b1 = nn1_b + layer * HD;
        ho = h + (size_t)(layer * NE + e) * HD;
    } else if (w < 2 * NE + 2 * NEC) {
        int w2 = w - 2 * NE;
        int layer = w2 / NEC, e = w2 - layer * NEC;
        ef = ef_c + (size_t)e * EDIM;
        w1 = cnn1_w + layer * EDIM * HD;
        b1 = cnn1_b + layer * HD;
        ho = h + (size_t)(2 * NE + layer * NEC + e) * HD;
    } else return;

    float ev = (lane < EDIM) ? ef[lane] : 0.f;
    float acc = b1[lane];
#pragma unroll
    for (int j = 0; j < EDIM; j++)
        acc += __shfl_sync(0xffffffffu, ev, j) * w1[j * HD + lane];
    ho[lane] = fmaxf(acc, 0.f);
}

// ---------------- P = X @ T via HMMA; all 1024 cols per block + Q slice ------------
// blockIdx.y == 0 : 128 rows x 1024 cols of P; blockIdx.y == 1 : Q rows.
// Ts_all holds the full precomputed fp16 T (flat copy); X loaded/converted once.
__global__ void __launch_bounds__(256, 2)
k_gemmPQ(const float* __restrict__ X, int nrows,
         const __half* __restrict__ Tg, const float* __restrict__ b2,
         __half* __restrict__ P, float* __restrict__ Q) {
    int tid  = threadIdx.x;
    int row0 = blockIdx.x * 128;

    if (blockIdx.y == 1) {
        int wp = tid >> 5, lane = tid & 31;
        for (int it = 0; it < 16; it++) {
            int r = row0 + it * 8 + wp;
            if (r >= nrows) return;
            float xv = X[(size_t)r * HD + lane];
            float acc = 0.f;
#pragma unroll
            for (int i = 0; i < HD; i++)
                acc += __shfl_sync(0xffffffffu, xv, i) * b2[i * HD + lane];
            Q[(size_t)r * HD + lane] = acc;
        }
        return;
    }

    extern __shared__ __half smh[];
    __half* Xs = smh;                    // 128 * XPAD
    __half* Ts = smh + 128 * XPAD;       // 8 * 128 * XPAD (all column tiles)

    // load X tile -> fp16 (2 threads per row, 16 halves each)
    {
        int r  = tid >> 1;
        int hs = (tid & 1) * 16;
        int row = row0 + r;
        __half* dstp = Xs + r * XPAD + hs;
        if (row < nrows) {
            const float* srcp = X + (size_t)row * HD + hs;
#pragma unroll
            for (int j = 0; j < 16; j += 2)
                *(__half2*)(dstp + j) = __float22half2_rn(*(const float2*)(srcp + j));
        } else {
#pragma unroll
            for (int j = 0; j < 16; j += 2)
                *(__half2*)(dstp + j) = __half2half2(__float2half(0.f));
        }
    }
    // flat vectorized copy of the precomputed T (8 tiles, 81920 bytes)
    {
        const uint4* s4 = (const uint4*)Tg;
        uint4* d4 = (uint4*)Ts;
#pragma unroll
        for (int it = 0; it < 20; it++)
            d4[tid + 256 * it] = s4[tid + 256 * it];
    }
    __syncthreads();

    int warp = tid >> 5, lane = tid & 31;
    int wm = (warp >> 1) * 32;       // warp m offset (4 warps along M)
    int wn = (warp & 1) * 64;        // warp n offset (2 warps along N)
    int g  = lane >> 2;
    int tg = lane & 3;

    unsigned xs_base = (unsigned)__cvta_generic_to_shared(Xs);
    unsigned ts_base = (unsigned)__cvta_generic_to_shared(Ts);

    // A fragments hoisted: same for every column tile
    unsigned a[2][2][4];
#pragma unroll
    for (int ks = 0; ks < 2; ks++) {
        int k0 = ks * 16;
#pragma unroll
        for (int mt = 0; mt < 2; mt++) {
            int lrow = wm + mt * 16 + (lane & 15);
            int lk   = k0 + ((lane >> 4) << 3);
            unsigned addr = xs_base + (unsigned)(lrow * XPAD + lk) * 2u;
            asm volatile("ldmatrix.sync.aligned.m8n8.x4.shared.b16 {%0,%1,%2,%3}, [%4];"
                         : "=r"(a[ks][mt][0]), "=r"(a[ks][mt][1]),
                           "=r"(a[ks][mt][2]), "=r"(a[ks][mt][3])
                         : "r"(addr));
        }
    }

    for (int ct = 0; ct < 8; ct++) {
        unsigned tb = ts_base + (unsigned)(ct * TG_TILE) * 2u;

        float acc[2][8][4];
#pragma unroll
        for (int mt = 0; mt < 2; mt++)
#pragma unroll
            for (int nt = 0; nt < 8; nt++)
#pragma unroll
                for (int j = 0; j < 4; j++) acc[mt][nt][j] = 0.f;

#pragma unroll
        for (int ks = 0; ks < 2; ks++) {
            int k0 = ks * 16;
            unsigned b[8][2];
#pragma unroll
            for (int np = 0; np < 4; np++) {
                int nb = wn + np * 16;
                int quarter = lane >> 3;
                int nrow = nb + ((quarter >> 1) << 3) + (lane & 7);
                int kk   = k0 + ((quarter & 1) << 3);
                unsigned addr = tb + (unsigned)(nrow * XPAD + kk) * 2u;
                asm volatile("ldmatrix.sync.aligned.m8n8.x4.shared.b16 {%0,%1,%2,%3}, [%4];"
                             : "=r"(b[np * 2][0]), "=r"(b[np * 2][1]),
                               "=r"(b[np * 2 + 1][0]), "=r"(b[np * 2 + 1][1])
                             : "r"(addr));
            }
#pragma unroll
            for (int nt = 0; nt < 8; nt++) {
#pragma unroll
                for (int mt = 0; mt < 2; mt++) {
                    asm volatile(
                        "mma.sync.aligned.m16n8k16.row.col.f32.f16.f16.f32 "
                        "{%0,%1,%2,%3},{%4,%5,%6,%7},{%8,%9},{%0,%1,%2,%3};"
                        : "+f"(acc[mt][nt][0]), "+f"(acc[mt][nt][1]),
                          "+f"(acc[mt][nt][2]), "+f"(acc[mt][nt][3])
                        : "r"(a[ks][mt][0]), "r"(a[ks][mt][1]),
                          "r"(a[ks][mt][2]), "r"(a[ks][mt][3]),
                          "r"(b[nt][0]), "r"(b[nt][1]));
                }
            }
        }

        // store: thread (g,tg) owns 16 contiguous global halves per row
        int cb0 = ct * 128 + wn + tg * 16;
#pragma unroll
        for (int mt = 0; mt < 2; mt++) {
            int r1 = row0 + wm + mt * 16 + g;
            int r2 = r1 + 8;
            unsigned lo[8], hi[8];
#pragma unroll
            for (int nt = 0; nt < 8; nt++) {
                __half2 h1 = __floats2half2_rn(acc[mt][nt][0], acc[mt][nt][1]);
                __half2 h2 = __floats2half2_rn(acc[mt][nt][2], acc[mt][nt][3]);
                lo[nt] = *(unsigned*)&h1;
                hi[nt] = *(unsigned*)&h2;
            }
            if (r1 < nrows) {
                uint4* dp = (uint4*)(P + (size_t)r1 * (HD * HD) + cb0);
                dp[0] = make_uint4(lo[0], lo[1], lo[2], lo[3]);
                dp[1] = make_uint4(lo[4], lo[5], lo[6], lo[7]);
            }
            if (r2 < nrows) {
                uint4* dp = (uint4*)(P + (size_t)r2 * (HD * HD) + cb0);
                dp[0] = make_uint4(hi[0], hi[1], hi[2], hi[3]);
                dp[1] = make_uint4(hi[4], hi[5], hi[6], hi[7]);
            }
        }
    }
}

// ---------------- per-edge message + scatter-add (fp16 P gather, proven) ----------
__global__ void k_edge_msg(int nE, const int* __restrict__ src, const int* __restrict__ dst,
                           const float* __restrict__ h, const __half* __restrict__ P,
                           const float* __restrict__ Q, float* __restrict__ agg) {
    int e = (blockIdx.x * blockDim.x + threadIdx.x) >> 5;
    int lane = threadIdx.x & 31;
    if (e >= nE) return;
    int s = src[e];
    int d = dst[e];
    float hv = h[(size_t)e * HD + lane];
    const __half* Pr = P + (size_t)s * (HD * HD);
    int kq = lane >> 3;
    int og = lane & 7;

    float a0 = 0.f, a1 = 0.f, a2 = 0.f, a3 = 0.f;
#pragma unroll
    for (int it = 0; it < 8; it++) {
        int k = it * 4 + kq;
        float hk = __shfl_sync(0xffffffffu, hv, k);
        uint2 raw = *(const uint2*)(Pr + k * HD + og * 4);
        float2 f01 = __half22float2(*(__half2*)&raw.x);
        float2 f23 = __half22float2(*(__half2*)&raw.y);
        a0 += hk * f01.x; a1 += hk * f01.y; a2 += hk * f23.x; a3 += hk * f23.y;
    }
#pragma unroll
    for (int m = 8; m <= 16; m <<= 1) {
        a0 += __shfl_xor_sync(0xffffffffu, a0, m);
        a1 += __shfl_xor_sync(0xffffffffu, a1, m);
        a2 += __shfl_xor_sync(0xffffffffu, a2, m);
        a3 += __shfl_xor_sync(0xffffffffu, a3, m);
    }
    if (lane < 8) {
        float4 q = *(const float4*)(Q + (size_t)s * HD + lane * 4);
        float* ag = agg + (size_t)d * HD + lane * 4;
        atomicAdd(ag + 0, a0 + q.x);
        atomicAdd(ag + 1, a1 + q.y);
        atomicAdd(ag + 2, a2 + q.z);
        atomicAdd(ag + 3, a3 + q.w);
    }
}

// ---------------- finalize + project; re-zeros agg after consuming ----------------
__global__ void k_finalize_proj(const float* __restrict__ Xin, float* __restrict__ Xout,
                                float* __restrict__ agg, const int* __restrict__ deg,
                                const float* __restrict__ rw, const float* __restrict__ rb,
                                const float* __restrict__ pw, const float* __restrict__ pb,
                                float* __restrict__ m, int nrows,
                                float* __restrict__ copy_out) {
    __shared__ float Rs[HD][HD], Pw[HD][HD];
    for (int i = threadIdx.x; i < HD * HD; i += blockDim.x) {
        Rs[i >> 5][i & 31] = rw[i];
        Pw[i >> 5][i & 31] = pw[i];
    }
    __syncthreads();

    int r = (blockIdx.x * blockDim.x + threadIdx.x) >> 5;
    int lane = threadIdx.x & 31;
    if (r >= nrows) return;
    float xv = Xin[(size_t)r * HD + lane];
    float av = agg[(size_t)r * HD + lane];
    agg[(size_t)r * HD + lane] = 0.f;
    float acc = rb[lane] + av / fmaxf((float)deg[r], 1.f);
#pragma unroll
    for (int i = 0; i < HD; i++)
        acc += __shfl_sync(0xffffffffu, xv, i) * Rs[i][lane];
    float xn = fmaxf(acc, 0.f);
    Xout[(size_t)r * HD + lane] = xn;
    if (copy_out) copy_out[(size_t)r * HD + lane] = xn;
    float macc = pb[lane];
#pragma unroll
    for (int i = 0; i < HD; i++)
        macc += __shfl_sync(0xffffffffu, xn, i) * Pw[i][lane];
    m[(size_t)r * HD + lane] = macc;
}

// ---------------- CSR gather segment-mean + residual add --------------------------
__global__ void k_seg_mean_add(const float* __restrict__ in, float* __restrict__ outp,
                               const float* __restrict__ m,
                               const int* __restrict__ off, const int* __restrict__ csr,
                               int nrows) {
    int r = (blockIdx.x * blockDim.x + threadIdx.x) >> 5;
    int lane = threadIdx.x & 31;
    if (r >= nrows) return;
    int b = off[r], e2 = off[r + 1];
    float acc = 0.f;
    for (int j = b; j < e2; j++)
        acc += m[(size_t)csr[j] * HD + lane];
    outp[(size_t)r * HD + lane] =
        in[(size_t)r * HD + lane] + acc / fmaxf((float)(e2 - b), 1.f);
}

// ===================================================================================
static inline int cdiv(int a, int b) { return (a + b - 1) / b; }

extern "C" void kernel_launch(void* const* d_in, const int* in_sizes, int n_in,
                              void* d_out, int out_size) {
    const float* node_features   = (const float*)d_in[0];
    const int*   edge_index      = (const int*)d_in[1];
    const float* edge_features   = (const float*)d_in[2];
    const float* clique_features = (const float*)d_in[3];
    const int*   n2c_index       = (const int*)d_in[4];
    const int*   cedge_index     = (const int*)d_in[5];
    const float* cedge_features  = (const float*)d_in[6];
    const float* nn1_w  = (const float*)d_in[7];
    const float* nn1_b  = (const float*)d_in[8];
    const float* nn2_w  = (const float*)d_in[9];
    const float* nn2_b  = (const float*)d_in[10];
    const float* root_w = (const float*)d_in[11];
    const float* root_b = (const float*)d_in[12];
    const float* n2c_w  = (const float*)d_in[13];
    const float* n2c_b  = (const float*)d_in[14];
    const float* cnn1_w = (const float*)d_in[15];
    const float* cnn1_b = (const float*)d_in[16];
    const float* cnn2_w = (const float*)d_in[17];
    const float* cnn2_b = (const float*)d_in[18];
    const float* croot_w = (const float*)d_in[19];
    const float* croot_b = (const float*)d_in[20];
    const float* c2n_w  = (const float*)d_in[21];
    const float* c2n_b  = (const float*)d_in[22];
    float* out = (float*)d_out;

    const int* src  = edge_index;
    const int* dst  = edge_index + NE;
    const int* nid  = n2c_index;
    const int* cid  = n2c_index + NA;
    const int* csrc = cedge_index;
    const int* cdst = cedge_index + NEC;

    float *x, *c, *h, *Q, *aggn, *aggc, *m;
    __half *P, *Tg;
    int *deg, *cur, *off_c, *off_n, *csr_c, *csr_n;
    cudaGetSymbolAddress((void**)&x, g_x);
    cudaGetSymbolAddress((void**)&c, g_c);
    cudaGetSymbolAddress((void**)&h, g_h);
    cudaGetSymbolAddress((void**)&P, g_P);
    cudaGetSymbolAddress((void**)&Tg, g_T);
    cudaGetSymbolAddress((void**)&Q, g_Q);
    cudaGetSymbolAddress((void**)&aggn, g_aggn);
    cudaGetSymbolAddress((void**)&aggc, g_aggc);
    cudaGetSymbolAddress((void**)&m, g_m);
    cudaGetSymbolAddress((void**)&deg, g_deg);
    cudaGetSymbolAddress((void**)&cur, g_cur);
    cudaGetSymbolAddress((void**)&off_c, g_off_c);
    cudaGetSymbolAddress((void**)&off_n, g_off_n);
    cudaGetSymbolAddress((void**)&csr_c, g_csr_c);
    cudaGetSymbolAddress((void**)&csr_n, g_csr_n);
    const int* deg_dst  = deg;
    const int* deg_cdst = deg + NN;
    const int* deg_cid  = deg + NN + NCL;
    const int* deg_nid  = deg + NN + 2 * NCL;

    static bool attr_set = false;
    if (!attr_set) {
        cudaFuncSetAttribute(k_gemmPQ, cudaFuncAttributeMaxDynamicSharedMemorySize,
                             SMEM_GEMM);
        attr_set = true;
    }

    const int TB = 256;
    dim3 gemmGridN(cdiv(NN, 128), 2);   // y==1 is the Q slice
    dim3 gemmGridC(cdiv(NCL, 128), 2);

    // ---- launch order: gemmPQ is launch #4 -> profiled by ncu ----
    k_edge_mlp_all<<<cdiv((2 * NE + 2 * NEC) * 32, TB), TB>>>(
        edge_features, cedge_features, nn1_w, nn1_b, cnn1_w, cnn1_b, h);
    k_convT<<<cdiv(4 * 8 * 128 * 32, TB), TB>>>(nn2_w, cnn2_w, Tg);
    k_zero_setup<<<cdiv(2 * NN + 2 * NCL, TB), TB>>>(deg, cur);
    // 4: node gemm l0  <-- PROFILED
    k_gemmPQ<<<gemmGridN, 256, SMEM_GEMM>>>(node_features, NN, Tg, nn2_b, P, Q);
    k_edge_msg<<<cdiv(NE * 32, TB), TB>>>(NE, src, dst, h, P, Q, aggn);
    k_count_all<<<cdiv(NE + NEC + NA, TB), TB>>>(dst, cdst, nid, cid, deg);
    k_scan2<<<2, 1024>>>(deg_cid, NCL, off_c, deg_nid, NN, off_n);
    k_fill_csr<<<cdiv(NA, TB), TB>>>(nid, cid, off_c, off_n, cur, csr_c, csr_n);
    k_finalize_proj<<<cdiv(NN * 32, TB), TB>>>(node_features, x, aggn, deg_dst,
                                               root_w, root_b, n2c_w, n2c_b,
                                               m, NN, nullptr);
    k_seg_mean_add<<<cdiv(NCL * 32, TB), TB>>>(clique_features, c, m, off_c, csr_c, NCL);

    // ---- l0 clique conv ----
    k_gemmPQ<<<gemmGridC, 256, SMEM_GEMM>>>(c, NCL, Tg + 2 * TG_CONV, cnn2_b, P, Q);
    k_edge_msg<<<cdiv(NEC * 32, TB), TB>>>(NEC, csrc, cdst, h + (size_t)2 * NE * HD, P, Q, aggc);
    k_finalize_proj<<<cdiv(NCL * 32, TB), TB>>>(c, c, aggc, deg_cdst,
                                                croot_w, croot_b, c2n_w, c2n_b,
                                                m, NCL, nullptr);
    k_seg_mean_add<<<cdiv(NN * 32, TB), TB>>>(x, x, m, off_n, csr_n, NN);

    // ---- l1 node conv ----
    k_gemmPQ<<<gemmGridN, 256, SMEM_GEMM>>>(x, NN, Tg + 1 * TG_CONV, nn2_b + HD * HD, P, Q);
    k_edge_msg<<<cdiv(NE * 32, TB), TB>>>(NE, src, dst, h + (size_t)NE * HD, P, Q, aggn);
    k_finalize_proj<<<cdiv(NN * 32, TB), TB>>>(x, x, aggn, deg_dst,
                                               root_w + HD * HD, root_b + HD,
                                               n2c_w + HD * HD, n2c_b + HD,
                                               m, NN, nullptr);
    k_seg_mean_add<<<cdiv(NCL * 32, TB), TB>>>(c, c, m, off_c, csr_c, NCL);

    // ---- l1 clique conv ----
    k_gemmPQ<<<gemmGridC, 256, SMEM_GEMM>>>(c, NCL, Tg + 3 * TG_CONV, cnn2_b + HD * HD, P, Q);
    k_edge_msg<<<cdiv(NEC * 32, TB), TB>>>(NEC, csrc, cdst,
                                           h + (size_t)(2 * NE + NEC) * HD, P, Q, aggc);
    k_finalize_proj<<<cdiv(NCL * 32, TB), TB>>>(c, c, aggc, deg_cdst,
                                                croot_w + HD * HD, croot_b + HD,
                                                c2n_w + HD * HD, c2n_b + HD,
                                                m, NCL, out + (size_t)NN * HD);
    k_seg_mean_add<<<cdiv(NN * 32, TB), TB>>>(x, out, m, off_n, csr_n, NN);
}